// round 11
// baseline (speedup 1.0000x reference)
#include <cuda_runtime.h>
#include <cuda_fp16.h>
#include <math.h>
#include <stdint.h>

#define B_  2
#define T_  2048
#define D_  2048
#define NH_ 16
#define KH_ 4
#define H_  128

// Scratch (allocation-free rule: __device__ globals)
__device__ __half g_xqh [B_*T_*D_];
__device__ __half g_xkvh[B_*T_*D_];
__device__ __half g_wqt [NH_*H_*D_];
__device__ __half g_wkt [KH_*H_*D_];
__device__ __half g_wvt [KH_*H_*D_];
__device__ __half g_wot [D_*NH_*H_];
__device__ float  g_q  [B_*T_*NH_*H_];
__device__ float  g_k  [B_*T_*KH_*H_];
__device__ float  g_v  [B_*T_*KH_*H_];
__device__ __half g_qh [B_*T_*NH_*H_];
__device__ __half g_kh [B_*T_*KH_*H_];
__device__ __half g_vt [B_*KH_*H_*T_];
__device__ __half g_attn[B_*T_*NH_*H_];

__device__ __forceinline__ uint32_t f2h2(float lo, float hi) {
    __half2 h = __floats2half2_rn(lo, hi);
    return *(uint32_t*)&h;
}

__device__ __forceinline__ void cpasync16(void* dst, const void* src) {
    uint32_t d = (uint32_t)__cvta_generic_to_shared(dst);
    asm volatile("cp.async.cg.shared.global [%0], [%1], 16;\n" :: "r"(d), "l"(src));
}

__device__ __forceinline__ void mma16(float* c, const uint32_t* a, const uint32_t* b) {
    asm volatile(
        "mma.sync.aligned.m16n8k16.row.col.f32.f16.f16.f32 "
        "{%0,%1,%2,%3}, {%4,%5,%6,%7}, {%8,%9}, {%0,%1,%2,%3};\n"
        : "+f"(c[0]), "+f"(c[1]), "+f"(c[2]), "+f"(c[3])
        : "r"(a[0]), "r"(a[1]), "r"(a[2]), "r"(a[3]),
          "r"(b[0]), "r"(b[1]));
}

// ---------------------------------------------------------------------------
// Aux kernels
// ---------------------------------------------------------------------------
__global__ void cvt16_2(const float* __restrict__ s0, const float* __restrict__ s1,
                        __half2* __restrict__ d0, __half2* __restrict__ d1) {
    const float* s = blockIdx.z ? s1 : s0;
    __half2* d = blockIdx.z ? d1 : d0;
    int i = blockIdx.x * 256 + threadIdx.x;
    float4 a = ((const float4*)s)[i];
    d[2*i]   = __floats2half2_rn(a.x, a.y);
    d[2*i+1] = __floats2half2_rn(a.z, a.w);
}

__global__ void tr16(const float* __restrict__ src, __half* __restrict__ dst,
                     int R, int C) {
    __shared__ float tile[32][33];
    int c0 = blockIdx.x * 32, r0 = blockIdx.y * 32;
    int tx = threadIdx.x & 31, ty = threadIdx.x >> 5;
#pragma unroll
    for (int i = 0; i < 32; i += 8)
        tile[ty + i][tx] = src[(size_t)(r0 + ty + i) * C + c0 + tx];
    __syncthreads();
#pragma unroll
    for (int i = 0; i < 32; i += 8)
        dst[(size_t)(c0 + ty + i) * R + r0 + tx] = __float2half_rn(tile[tx][ty + i]);
}

__global__ void tr16_2(const float* __restrict__ s0, const float* __restrict__ s1,
                       __half* __restrict__ d0, __half* __restrict__ d1,
                       int R, int C) {
    __shared__ float tile[32][33];
    const float* src = blockIdx.z ? s1 : s0;
    __half* dst = blockIdx.z ? d1 : d0;
    int c0 = blockIdx.x * 32, r0 = blockIdx.y * 32;
    int tx = threadIdx.x & 31, ty = threadIdx.x >> 5;
#pragma unroll
    for (int i = 0; i < 32; i += 8)
        tile[ty + i][tx] = src[(size_t)(r0 + ty + i) * C + c0 + tx];
    __syncthreads();
#pragma unroll
    for (int i = 0; i < 32; i += 8)
        dst[(size_t)(c0 + ty + i) * R + r0 + tx] = __float2half_rn(tile[tx][ty + i]);
}

__global__ void trv(const float* __restrict__ v, __half* __restrict__ vt) {
    __shared__ float tile[32][33];
    int bk = blockIdx.z, b = bk >> 2, kh = bk & 3;
    int t0 = blockIdx.x * 32, h0 = blockIdx.y * 32;
    int tx = threadIdx.x & 31, ty = threadIdx.x >> 5;
#pragma unroll
    for (int i = 0; i < 32; i += 8)
        tile[ty + i][tx] =
            v[(((size_t)(b * T_ + t0 + ty + i)) * KH_ + kh) * H_ + h0 + tx];
    __syncthreads();
#pragma unroll
    for (int i = 0; i < 32; i += 8)
        vt[((size_t)(b * KH_ + kh) * H_ + h0 + ty + i) * T_ + t0 + tx] =
            __float2half_rn(tile[tx][ty + i]);
}

// ---------------------------------------------------------------------------
// RoPE
// ---------------------------------------------------------------------------
__global__ void rope_q16(const float* __restrict__ x, __half* __restrict__ y,
                         const int* __restrict__ pos, float scale) {
    int token = blockIdx.x;
    int ng = blockIdx.y * 4;
    int i = threadIdx.x;
    double ts = exp(((double)i / 64.0) * 9.210340371976182736);
    float p = (float)pos[token];
    float angf = p / (float)ts;
    double s_, c_;
    sincos((double)angf, &s_, &c_);
    float s = (float)s_, c = (float)c_;
    const float* base = x + (size_t)token * NH_ * H_;
    __half* dst = y + (size_t)token * NH_ * H_;
#pragma unroll
    for (int n = ng; n < ng + 4; n++) {
        float x1 = base[n * H_ + i];
        float x2 = base[n * H_ + i + 64];
        dst[n * H_ + i]      = __float2half_rn((x1 * c - x2 * s) * scale);
        dst[n * H_ + i + 64] = __float2half_rn((x2 * c + x1 * s) * scale);
    }
}

__global__ void rope_k16(const float* __restrict__ x, __half* __restrict__ y,
                         const int* __restrict__ pos) {
    int token = blockIdx.x;
    int i = threadIdx.x;
    double ts = exp(((double)i / 64.0) * 9.210340371976182736);
    float p = (float)pos[token];
    float angf = p / (float)ts;
    double s_, c_;
    sincos((double)angf, &s_, &c_);
    float s = (float)s_, c = (float)c_;
    const float* base = x + (size_t)token * KH_ * H_;
    __half* dst = y + (size_t)token * KH_ * H_;
#pragma unroll
    for (int n = 0; n < KH_; n++) {
        float x1 = base[n * H_ + i];
        float x2 = base[n * H_ + i + 64];
        dst[n * H_ + i]      = __float2half_rn(x1 * c - x2 * s);
        dst[n * H_ + i + 64] = __float2half_rn(x2 * c + x1 * s);
    }
}

// ---------------------------------------------------------------------------
// FP16 tensor-core GEMM (R7, unchanged)
// ---------------------------------------------------------------------------
#define GST 20

__device__ __forceinline__
void gemm16_body(const uint32_t* __restrict__ A, const uint32_t* __restrict__ Bt,
                 float* __restrict__ C, int M, int Nc, int Kd) {
    __shared__ uint32_t As[2][128 * GST];
    __shared__ uint32_t Bs[2][128 * GST];
    int tid  = threadIdx.x;
    int brow = blockIdx.y * 128, bcol = blockIdx.x * 128;
    int warp = tid >> 5, lane = tid & 31;
    int mw = (warp >> 2) * 64, nw = (warp & 3) * 32;
    int lr = lane >> 2, lc = lane & 3;
    int KW = Kd >> 1;

    float acc[4][4][4];
#pragma unroll
    for (int mi = 0; mi < 4; mi++)
#pragma unroll
        for (int ni = 0; ni < 4; ni++)
#pragma unroll
            for (int j = 0; j < 4; j++) acc[mi][ni][j] = 0.f;

    const int nkt = Kd >> 5;

    auto load_stage = [&](int kt, int buf) {
        int kw0 = kt * 16;
#pragma unroll
        for (int u = 0; u < 2; u++) {
            int c = tid + 256 * u;
            int row = c >> 2, w4 = (c & 3) * 4;
            cpasync16(&As[buf][row * GST + w4],
                      &A[(size_t)(brow + row) * KW + kw0 + w4]);
            cpasync16(&Bs[buf][row * GST + w4],
                      &Bt[(size_t)(bcol + row) * KW + kw0 + w4]);
        }
    };

    load_stage(0, 0);
    asm volatile("cp.async.commit_group;\n");

    for (int kt = 0; kt < nkt; kt++) {
        int buf = kt & 1;
        if (kt + 1 < nkt) {
            load_stage(kt + 1, buf ^ 1);
            asm volatile("cp.async.commit_group;\n");
            asm volatile("cp.async.wait_group 1;\n");
        } else {
            asm volatile("cp.async.wait_group 0;\n");
        }
        __syncthreads();

#pragma unroll
        for (int ks = 0; ks < 2; ks++) {
            uint32_t af[4][4], bf[4][2];
#pragma unroll
            for (int mi = 0; mi < 4; mi++) {
                const uint32_t* p = &As[buf][(mw + mi * 16 + lr) * GST + ks * 8 + lc];
                af[mi][0] = p[0];
                af[mi][1] = p[8 * GST];
                af[mi][2] = p[4];
                af[mi][3] = p[8 * GST + 4];
            }
#pragma unroll
            for (int ni = 0; ni < 4; ni++) {
                const uint32_t* p = &Bs[buf][(nw + ni * 8 + lr) * GST + ks * 8 + lc];
                bf[ni][0] = p[0];
                bf[ni][1] = p[4];
            }
#pragma unroll
            for (int mi = 0; mi < 4; mi++)
#pragma unroll
                for (int ni = 0; ni < 4; ni++)
                    mma16(acc[mi][ni], af[mi], bf[ni]);
        }
        __syncthreads();
    }

#pragma unroll
    for (int mi = 0; mi < 4; mi++) {
#pragma unroll
        for (int ni = 0; ni < 4; ni++) {
            int r0 = brow + mw + mi * 16 + lr;
            int cc = bcol + nw + ni * 8 + lc * 2;
            *(float2*)&C[(size_t)r0 * Nc + cc] =
                make_float2(acc[mi][ni][0], acc[mi][ni][1]);
            *(float2*)&C[(size_t)(r0 + 8) * Nc + cc] =
                make_float2(acc[mi][ni][2], acc[mi][ni][3]);
        }
    }
}

__global__ __launch_bounds__(256, 2)
void gemm16(const uint32_t* __restrict__ A, const uint32_t* __restrict__ Bt,
            float* __restrict__ C, int M, int Nc, int Kd) {
    gemm16_body(A, Bt, C, M, Nc, Kd);
}

__global__ __launch_bounds__(256, 2)
void gemm16_kv(const uint32_t* __restrict__ A,
               const uint32_t* __restrict__ B0, const uint32_t* __restrict__ B1,
               float* __restrict__ C0, float* __restrict__ C1,
               int M, int Nc, int Kd) {
    gemm16_body(A, blockIdx.z ? B1 : B0, blockIdx.z ? C1 : C0, M, Nc, Kd);
}

// ---------------------------------------------------------------------------
// FP16 flash attention: Q tile 128 (smem-resident), KV tile 64, 2 blocks/SM.
// P never touches smem: S C-frags repacked in place as PV A-frags.
//   Qs [128][68], Ks [2][64][68], Vs(=V^T) [2][128][36]. 104KB total.
// ---------------------------------------------------------------------------
#define QST 68
#define KST 68
#define VSTW 36
#define FA_SMEM ((128*QST + 2*64*KST + 2*128*VSTW) * 4)

__global__ __launch_bounds__(256, 2)
void flash16(const uint32_t* __restrict__ qh, const uint32_t* __restrict__ kk,
             const uint32_t* __restrict__ vt, uint32_t* __restrict__ o) {
    extern __shared__ uint32_t sm_u[];
    uint32_t* Qs = sm_u;                  // [128][QST]
    uint32_t* Ks = Qs + 128 * QST;        // [2][64*KST]
    uint32_t* Vs = Ks + 2 * 64 * KST;     // [2][128*VSTW]

    int qt = (int)gridDim.x - 1 - (int)blockIdx.x;  // big tiles first
    int n  = blockIdx.y;
    int b  = blockIdx.z;
    int khd = n >> 2;
    int tid = threadIdx.x, warp = tid >> 5, lane = tid & 31;
    int lr = lane >> 2, lc = lane & 3;
    int q0 = qt * 128;

    // ---- load Q tile into resident smem (128 rows x 64 words) ----
#pragma unroll
    for (int u = 0; u < 8; u++) {
        int f = tid + 256 * u;
        int r = f >> 4, w4 = (f & 15) * 4;
        *(uint4*)(Qs + r * QST + w4) = *(const uint4*)(qh +
            ((size_t)((b * T_ + q0 + r) * NH_ + n) << 6) + w4);
    }

    float m_[2] = {-1e30f, -1e30f};
    float l_[2] = {0.f, 0.f};
    float oacc[16][4];
#pragma unroll
    for (int ns = 0; ns < 16; ns++)
#pragma unroll
        for (int j = 0; j < 4; j++) oacc[ns][j] = 0.f;

    int row0 = q0 + warp * 16 + lr;
    int njt = 2 * qt + 2;
    const uint32_t* qrow = Qs + (warp * 16 + lr) * QST + lc;

    auto load_kv = [&](int jt, int bufsel) {
        int s0 = jt * 64;
        uint32_t* Kd = Ks + bufsel * 64 * KST;
        uint32_t* Vd = Vs + bufsel * 128 * VSTW;
#pragma unroll
        for (int u = 0; u < 4; u++) {
            int f = tid + 256 * u;
            int r = f >> 4, w4 = (f & 15) * 4;          // K: 64 rows x 16 chunks
            cpasync16(Kd + r * KST + w4,
                      kk + ((size_t)((b * T_ + s0 + r) * KH_ + khd) << 6) + w4);
            int hr = f >> 3, vw4 = (f & 7) * 4;         // V^T: 128 rows x 8 chunks
            cpasync16(Vd + hr * VSTW + vw4,
                      vt + ((((size_t)(b * KH_ + khd) * H_ + hr) * T_ + s0) >> 1) + vw4);
        }
    };

    load_kv(0, 0);
    asm volatile("cp.async.commit_group;\n");

    for (int jt = 0; jt < njt; jt++) {
        int buf = jt & 1;
        if (jt + 1 < njt) {
            load_kv(jt + 1, buf ^ 1);
            asm volatile("cp.async.commit_group;\n");
            asm volatile("cp.async.wait_group 1;\n");
        } else {
            asm volatile("cp.async.wait_group 0;\n");
        }
        __syncthreads();

        const uint32_t* Kb = Ks + buf * 64 * KST;
        const uint32_t* Vb = Vs + buf * 128 * VSTW;
        int s0 = jt * 64;

        // ---- S = Q K^T (Q frags reloaded from resident smem per hs) ----
        float s_[8][4];
#pragma unroll
        for (int ns = 0; ns < 8; ns++)
#pragma unroll
            for (int j = 0; j < 4; j++) s_[ns][j] = 0.f;
#pragma unroll
        for (int hs = 0; hs < 8; hs++) {
            const uint32_t* qp = qrow + hs * 8;
            uint32_t qf[4] = {qp[0], qp[8 * QST], qp[4], qp[8 * QST + 4]};
#pragma unroll
            for (int ns = 0; ns < 8; ns++) {
                const uint32_t* p = Kb + (ns * 8 + lr) * KST + hs * 8 + lc;
                uint32_t bf[2] = {p[0], p[4]};
                mma16(s_[ns], qf, bf);
            }
        }

        // ---- causal mask (last two kv tiles cross the diagonal) ----
        if (jt >= 2 * qt) {
#pragma unroll
            for (int ns = 0; ns < 8; ns++) {
                int col = s0 + ns * 8 + 2 * lc;
                if (col > row0)     s_[ns][0] = -1e30f;
                if (col + 1 > row0) s_[ns][1] = -1e30f;
                if (col > row0 + 8)     s_[ns][2] = -1e30f;
                if (col + 1 > row0 + 8) s_[ns][3] = -1e30f;
            }
        }

        // ---- online softmax; P packed in place into s_ (C-frag == A-frag) ----
        float mx0 = -1e30f, mx1 = -1e30f;
#pragma unroll
        for (int ns = 0; ns < 8; ns++) {
            mx0 = fmaxf(mx0, fmaxf(s_[ns][0], s_[ns][1]));
            mx1 = fmaxf(mx1, fmaxf(s_[ns][2], s_[ns][3]));
        }
        mx0 = fmaxf(mx0, __shfl_xor_sync(0xffffffffu, mx0, 1));
        mx0 = fmaxf(mx0, __shfl_xor_sync(0xffffffffu, mx0, 2));
        mx1 = fmaxf(mx1, __shfl_xor_sync(0xffffffffu, mx1, 1));
        mx1 = fmaxf(mx1, __shfl_xor_sync(0xffffffffu, mx1, 2));
        float mn0 = fmaxf(m_[0], mx0), mn1 = fmaxf(m_[1], mx1);
        float a0 = __expf(m_[0] - mn0), a1 = __expf(m_[1] - mn1);
        float sum0 = 0.f, sum1 = 0.f;
#pragma unroll
        for (int ns = 0; ns < 8; ns++) {
            float p0 = __expf(s_[ns][0] - mn0);
            float p1 = __expf(s_[ns][1] - mn0);
            float p2 = __expf(s_[ns][2] - mn1);
            float p3 = __expf(s_[ns][3] - mn1);
            sum0 += p0 + p1;
            sum1 += p2 + p3;
            s_[ns][0] = __uint_as_float(f2h2(p0, p1));  // rows lr   (a0 src)
            s_[ns][1] = __uint_as_float(f2h2(p2, p3));  // rows lr+8 (a1 src)
        }
        sum0 += __shfl_xor_sync(0xffffffffu, sum0, 1);
        sum0 += __shfl_xor_sync(0xffffffffu, sum0, 2);
        sum1 += __shfl_xor_sync(0xffffffffu, sum1, 1);
        sum1 += __shfl_xor_sync(0xffffffffu, sum1, 2);
        l_[0] = l_[0] * a0 + sum0;
        l_[1] = l_[1] * a1 + sum1;
        m_[0] = mn0; m_[1] = mn1;

#pragma unroll
        for (int ns = 0; ns < 16; ns++) {
            oacc[ns][0] *= a0; oacc[ns][1] *= a0;
            oacc[ns][2] *= a1; oacc[ns][3] *= a1;
        }

        // ---- O += P V  (P from registers, V frags from smem) ----
#pragma unroll
        for (int ks = 0; ks < 4; ks++) {
            uint32_t af[4] = {__float_as_uint(s_[2 * ks][0]),
                              __float_as_uint(s_[2 * ks][1]),
                              __float_as_uint(s_[2 * ks + 1][0]),
                              __float_as_uint(s_[2 * ks + 1][1])};
#pragma unroll
            for (int ns = 0; ns < 16; ns++) {
                const uint32_t* vp = Vb + (ns * 8 + lr) * VSTW + ks * 8 + lc;
                uint32_t bf[2] = {vp[0], vp[4]};
                mma16(oacc[ns], af, bf);
            }
        }
        __syncthreads();
    }

    // ---- epilogue: normalize, store fp16 (b,t,n,h) ----
    float inv0 = 1.f / l_[0], inv1 = 1.f / l_[1];
    size_t wb0 = ((size_t)((b * T_ + row0) * NH_ + n) << 6);
    size_t wb1 = ((size_t)((b * T_ + row0 + 8) * NH_ + n) << 6);
#pragma unroll
    for (int ns = 0; ns < 16; ns++) {
        o[wb0 + ns * 4 + lc] = f2h2(oacc[ns][0] * inv0, oacc[ns][1] * inv0);
        o[wb1 + ns * 4 + lc] = f2h2(oacc[ns][2] * inv1, oacc[ns][3] * inv1);
    }
}

// ---------------------------------------------------------------------------
extern "C" void kernel_launch(void* const* d_in, const int* in_sizes, int n_in,
                              void* d_out, int out_size) {
    const float* Xq   = (const float*)d_in[0];
    const float* Xkv  = (const float*)d_in[1];
    const int*   qpos = (const int*)  d_in[2];
    const int*   kpos = (const int*)  d_in[3];
    const float* Wq   = (const float*)d_in[4];
    const float* Wk   = (const float*)d_in[5];
    const float* Wv   = (const float*)d_in[6];
    const float* Wo   = (const float*)d_in[7];
    float* out = (float*)d_out;

    __half *xqh, *xkvh, *wqt, *wkt, *wvt, *wot, *qh, *kh, *vt, *attn;
    float *pq, *pk, *pv;
    cudaGetSymbolAddress((void**)&xqh,  g_xqh);
    cudaGetSymbolAddress((void**)&xkvh, g_xkvh);
    cudaGetSymbolAddress((void**)&wqt,  g_wqt);
    cudaGetSymbolAddress((void**)&wkt,  g_wkt);
    cudaGetSymbolAddress((void**)&wvt,  g_wvt);
    cudaGetSymbolAddress((void**)&wot,  g_wot);
    cudaGetSymbolAddress((void**)&pq,   g_q);
    cudaGetSymbolAddress((void**)&pk,   g_k);
    cudaGetSymbolAddress((void**)&pv,   g_v);
    cudaGetSymbolAddress((void**)&qh,   g_qh);
    cudaGetSymbolAddress((void**)&kh,   g_kh);
    cudaGetSymbolAddress((void**)&vt,   g_vt);
    cudaGetSymbolAddress((void**)&attn, g_attn);

    const int M = B_ * T_;  // 4096
    const int NHH = NH_ * H_, KHH = KH_ * H_;
    const float scale = 0.08838834764831845f; // 1/sqrt(128)

    // inputs -> fp16
    cvt16_2<<<dim3((B_*T_*D_) / 1024, 1, 2), 256>>>(
        Xq, Xkv, (__half2*)xqh, (__half2*)xkvh);
    // weights -> fp16 transposed
    tr16<<<dim3(NHH / 32, D_ / 32), 256>>>(Wq, wqt, D_, NHH);
    tr16_2<<<dim3(KHH / 32, D_ / 32, 2), 256>>>(Wk, Wv, wkt, wvt, D_, KHH);
    tr16<<<dim3(D_ / 32, NHH / 32), 256>>>(Wo, wot, NHH, D_);

    // projections
    gemm16<<<dim3(NHH / 128, M / 128), 256>>>(
        (const uint32_t*)xqh, (const uint32_t*)wqt, pq, M, NHH, D_);
    gemm16_kv<<<dim3(KHH / 128, M / 128, 2), 256>>>(
        (const uint32_t*)xkvh, (const uint32_t*)wkt, (const uint32_t*)wvt,
        pk, pv, M, KHH, D_);

    // rope (fp32 -> fp16), V transpose
    rope_q16<<<dim3(M, 4), 64>>>(pq, qh, qpos, scale);
    rope_k16<<<M, 64>>>(pk, kh, kpos);
    trv<<<dim3(T_ / 32, H_ / 32, B_ * KH_), 256>>>(pv, vt);

    // flash attention (fp16 mma.sync, KV 64, 2 blocks/SM)
    cudaFuncSetAttribute(flash16,
                         cudaFuncAttributeMaxDynamicSharedMemorySize, FA_SMEM);
    flash16<<<dim3(T_ / 128, NH_, B_), 256, FA_SMEM>>>(
        (const uint32_t*)qh, (const uint32_t*)kh, (const uint32_t*)vt,
        (uint32_t*)attn);

    // output projection
    gemm16<<<dim3(D_ / 128, M / 128), 256>>>(
        (const uint32_t*)attn, (const uint32_t*)wot, out, M, D_, NHH);
}

// round 12
// speedup vs baseline: 1.0407x; 1.0407x over previous
#include <cuda_runtime.h>
#include <cuda_fp16.h>
#include <math.h>
#include <stdint.h>

#define B_  2
#define T_  2048
#define D_  2048
#define NH_ 16
#define KH_ 4
#define H_  128

// Scratch (allocation-free rule: __device__ globals)
__device__ __half g_xqh [B_*T_*D_];        // Xq  fp16
__device__ __half g_xkvh[B_*T_*D_];        // Xkv fp16
__device__ __half g_wqt [NH_*H_*D_];       // Wq^T  fp16 [NHH][D]
__device__ __half g_wkt [KH_*H_*D_];       // Wk^T  fp16 [KHH][D]
__device__ __half g_wvt [KH_*H_*D_];       // Wv^T  fp16 [KHH][D]
__device__ __half g_wot [D_*NH_*H_];       // Wo^T  fp16 [D][NHH]
__device__ float2 g_scq [B_*T_*64];        // q sin/cos table
__device__ float2 g_sck [B_*T_*64];        // k sin/cos table
__device__ __half g_qh [B_*T_*NH_*H_];     // q rope'd, scaled, fp16 (b,t,n,h)
__device__ __half g_kh [B_*T_*KH_*H_];     // k rope'd fp16 (b,t,k,h)
__device__ __half g_vt [B_*KH_*H_*T_];     // v fp16 transposed (b,k,h,t)
__device__ __half g_attn[B_*T_*NH_*H_];    // attn out fp16 (b,t,n,h)

__device__ __forceinline__ uint32_t f2h2(float lo, float hi) {
    __half2 h = __floats2half2_rn(lo, hi);
    return *(uint32_t*)&h;
}

__device__ __forceinline__ void cpasync16(void* dst, const void* src) {
    uint32_t d = (uint32_t)__cvta_generic_to_shared(dst);
    asm volatile("cp.async.cg.shared.global [%0], [%1], 16;\n" :: "r"(d), "l"(src));
}

__device__ __forceinline__ void mma16(float* c, const uint32_t* a, const uint32_t* b) {
    asm volatile(
        "mma.sync.aligned.m16n8k16.row.col.f32.f16.f16.f32 "
        "{%0,%1,%2,%3}, {%4,%5,%6,%7}, {%8,%9}, {%0,%1,%2,%3};\n"
        : "+f"(c[0]), "+f"(c[1]), "+f"(c[2]), "+f"(c[3])
        : "r"(a[0]), "r"(a[1]), "r"(a[2]), "r"(a[3]),
          "r"(b[0]), "r"(b[1]));
}

// ---------------------------------------------------------------------------
// Aux kernels
// ---------------------------------------------------------------------------
__global__ void cvt16(const float* __restrict__ s, __half2* __restrict__ d) {
    int i = blockIdx.x * 256 + threadIdx.x;
    float4 a = ((const float4*)s)[i];
    d[2*i]   = __floats2half2_rn(a.x, a.y);
    d[2*i+1] = __floats2half2_rn(a.z, a.w);
}

__global__ void tr16(const float* __restrict__ src, __half* __restrict__ dst,
                     int R, int C) {
    __shared__ float tile[32][33];
    int c0 = blockIdx.x * 32, r0 = blockIdx.y * 32;
    int tx = threadIdx.x & 31, ty = threadIdx.x >> 5;
#pragma unroll
    for (int i = 0; i < 32; i += 8)
        tile[ty + i][tx] = src[(size_t)(r0 + ty + i) * C + c0 + tx];
    __syncthreads();
#pragma unroll
    for (int i = 0; i < 32; i += 8)
        dst[(size_t)(c0 + ty + i) * R + r0 + tx] = __float2half_rn(tile[tx][ty + i]);
}

// sin/cos tables for rope (exact same double-precision math as before)
__global__ void ropetab(const int* __restrict__ qpos, const int* __restrict__ kpos,
                        float2* __restrict__ scq, float2* __restrict__ sck) {
    int token = blockIdx.x;
    int i = threadIdx.x;  // 0..63
    double ts = exp(((double)i / 64.0) * 9.210340371976182736);
    double s_, c_;
    float angq = (float)qpos[token] / (float)ts;
    sincos((double)angq, &s_, &c_);
    scq[token * 64 + i] = make_float2((float)s_, (float)c_);
    float angk = (float)kpos[token] / (float)ts;
    sincos((double)angk, &s_, &c_);
    sck[token * 64 + i] = make_float2((float)s_, (float)c_);
}

// ---------------------------------------------------------------------------
// Shared fp16 GEMM mainloop: acc[4][4][4] = A[128 rows] @ Bt[128 cols]^T
// pool: 10240 uint32 words of smem (As | Bs, double-buffered).
// ---------------------------------------------------------------------------
#define GST 20
#define CST 133

__device__ __forceinline__
void gemm_mainloop(const uint32_t* __restrict__ A, const uint32_t* __restrict__ Bt,
                   int Kd, uint32_t* pool, float acc[4][4][4],
                   int brow, int bcol) {
    uint32_t* As = pool;          // [2][128*GST]
    uint32_t* Bs = pool + 5120;   // [2][128*GST]
    int tid  = threadIdx.x;
    int warp = tid >> 5, lane = tid & 31;
    int mw = (warp >> 2) * 64, nw = (warp & 3) * 32;
    int lr = lane >> 2, lc = lane & 3;
    int KW = Kd >> 1;

#pragma unroll
    for (int mi = 0; mi < 4; mi++)
#pragma unroll
        for (int ni = 0; ni < 4; ni++)
#pragma unroll
            for (int j = 0; j < 4; j++) acc[mi][ni][j] = 0.f;

    const int nkt = Kd >> 5;

    auto load_stage = [&](int kt, int buf) {
        int kw0 = kt * 16;
#pragma unroll
        for (int u = 0; u < 2; u++) {
            int c = tid + 256 * u;
            int row = c >> 2, w4 = (c & 3) * 4;
            cpasync16(&As[buf * 2560 + row * GST + w4],
                      &A[(size_t)(brow + row) * KW + kw0 + w4]);
            cpasync16(&Bs[buf * 2560 + row * GST + w4],
                      &Bt[(size_t)(bcol + row) * KW + kw0 + w4]);
        }
    };

    load_stage(0, 0);
    asm volatile("cp.async.commit_group;\n");

    for (int kt = 0; kt < nkt; kt++) {
        int buf = kt & 1;
        if (kt + 1 < nkt) {
            load_stage(kt + 1, buf ^ 1);
            asm volatile("cp.async.commit_group;\n");
            asm volatile("cp.async.wait_group 1;\n");
        } else {
            asm volatile("cp.async.wait_group 0;\n");
        }
        __syncthreads();

#pragma unroll
        for (int ks = 0; ks < 2; ks++) {
            uint32_t af[4][4], bf[4][2];
#pragma unroll
            for (int mi = 0; mi < 4; mi++) {
                const uint32_t* p = &As[buf * 2560 + (mw + mi * 16 + lr) * GST + ks * 8 + lc];
                af[mi][0] = p[0];
                af[mi][1] = p[8 * GST];
                af[mi][2] = p[4];
                af[mi][3] = p[8 * GST + 4];
            }
#pragma unroll
            for (int ni = 0; ni < 4; ni++) {
                const uint32_t* p = &Bs[buf * 2560 + (nw + ni * 8 + lr) * GST + ks * 8 + lc];
                bf[ni][0] = p[0];
                bf[ni][1] = p[4];
            }
#pragma unroll
            for (int mi = 0; mi < 4; mi++)
#pragma unroll
                for (int ni = 0; ni < 4; ni++)
                    mma16(acc[mi][ni], af[mi], bf[ni]);
        }
        __syncthreads();
    }
}

// stage one 64-row pass of the C tile into Cs (warps with mw==64p own it)
__device__ __forceinline__
void stage_pass(float* Cs, float acc[4][4][4], int p) {
    int tid = threadIdx.x, warp = tid >> 5, lane = tid & 31;
    int nw = (warp & 3) * 32;
    int lr = lane >> 2, lc = lane & 3;
    if ((warp >> 2) == p) {
#pragma unroll
        for (int mi = 0; mi < 4; mi++) {
#pragma unroll
            for (int ni = 0; ni < 4; ni++) {
                int r0 = mi * 16 + lr, cc = nw + ni * 8 + 2 * lc;
                Cs[r0 * CST + cc]           = acc[mi][ni][0];
                Cs[r0 * CST + cc + 1]       = acc[mi][ni][1];
                Cs[(r0 + 8) * CST + cc]     = acc[mi][ni][2];
                Cs[(r0 + 8) * CST + cc + 1] = acc[mi][ni][3];
            }
        }
    }
}

// ---------------------------------------------------------------------------
// Plain GEMM (output projection): C fp32
// ---------------------------------------------------------------------------
__global__ __launch_bounds__(256, 2)
void gemm16(const uint32_t* __restrict__ A, const uint32_t* __restrict__ Bt,
            float* __restrict__ C, int Nc, int Kd) {
    __shared__ uint32_t pool[10240];
    float acc[4][4][4];
    int brow = blockIdx.y * 128, bcol = blockIdx.x * 128;
    gemm_mainloop(A, Bt, Kd, pool, acc, brow, bcol);

    int tid = threadIdx.x, warp = tid >> 5, lane = tid & 31;
    int mw = (warp >> 2) * 64, nw = (warp & 3) * 32;
    int lr = lane >> 2, lc = lane & 3;
#pragma unroll
    for (int mi = 0; mi < 4; mi++) {
#pragma unroll
        for (int ni = 0; ni < 4; ni++) {
            int r0 = brow + mw + mi * 16 + lr;
            int cc = bcol + nw + ni * 8 + lc * 2;
            *(float2*)&C[(size_t)r0 * Nc + cc] =
                make_float2(acc[mi][ni][0], acc[mi][ni][1]);
            *(float2*)&C[(size_t)(r0 + 8) * Nc + cc] =
                make_float2(acc[mi][ni][2], acc[mi][ni][3]);
        }
    }
}

// ---------------------------------------------------------------------------
// Q projection + fused rope + scale -> fp16 (b,t,n,h)
// ---------------------------------------------------------------------------
__global__ __launch_bounds__(256, 2)
void gemm16_qrope(const uint32_t* __restrict__ A, const uint32_t* __restrict__ Bt,
                  __half* __restrict__ dst, const float2* __restrict__ sc,
                  int Kd, float scale) {
    __shared__ uint32_t pool[10240];
    float acc[4][4][4];
    int brow = blockIdx.y * 128, bcol = blockIdx.x * 128;
    gemm_mainloop(A, Bt, Kd, pool, acc, brow, bcol);

    float* Cs = (float*)pool;
    int tid = threadIdx.x;
    int n = bcol >> 7;  // head index
#pragma unroll
    for (int p = 0; p < 2; p++) {
        stage_pass(Cs, acc, p);
        __syncthreads();
        int row = tid >> 2, g = tid & 3;
        int token = brow + p * 64 + row;
        const float2* scrow = sc + (size_t)token * 64;
        __half* drow = dst + (((size_t)token * NH_ + n) << 7);
#pragma unroll
        for (int j = 0; j < 16; j++) {
            int i = g * 16 + j;
            float2 scv = scrow[i];
            float x1 = Cs[row * CST + i];
            float x2 = Cs[row * CST + i + 64];
            drow[i]      = __float2half_rn((x1 * scv.y - x2 * scv.x) * scale);
            drow[i + 64] = __float2half_rn((x2 * scv.y + x1 * scv.x) * scale);
        }
        __syncthreads();
    }
}

// ---------------------------------------------------------------------------
// K/V projection fused: z=0 -> K rope -> fp16 (b,t,k,h);
//                       z=1 -> V transpose -> fp16 (b,k,h,t)
// ---------------------------------------------------------------------------
__global__ __launch_bounds__(256, 2)
void gemm16_kvf(const uint32_t* __restrict__ A,
                const uint32_t* __restrict__ B0, const uint32_t* __restrict__ B1,
                __half* __restrict__ kdst, __half* __restrict__ vdst,
                const float2* __restrict__ sc, int Kd) {
    __shared__ uint32_t pool[10240];
    float acc[4][4][4];
    int brow = blockIdx.y * 128, bcol = blockIdx.x * 128;
    int isv = blockIdx.z;
    gemm_mainloop(A, isv ? B1 : B0, Kd, pool, acc, brow, bcol);

    float* Cs = (float*)pool;
    int tid = threadIdx.x;
    int kh = bcol >> 7;  // kv head
#pragma unroll
    for (int p = 0; p < 2; p++) {
        stage_pass(Cs, acc, p);
        __syncthreads();
        if (!isv) {
            // K rope
            int row = tid >> 2, g = tid & 3;
            int token = brow + p * 64 + row;
            const float2* scrow = sc + (size_t)token * 64;
            __half* drow = kdst + (((size_t)token * KH_ + kh) << 7);
#pragma unroll
            for (int j = 0; j < 16; j++) {
                int i = g * 16 + j;
                float2 scv = scrow[i];
                float x1 = Cs[row * CST + i];
                float x2 = Cs[row * CST + i + 64];
                drow[i]      = __float2half_rn(x1 * scv.y - x2 * scv.x);
                drow[i + 64] = __float2half_rn(x2 * scv.y + x1 * scv.x);
            }
        } else {
            // V transpose: rows=tokens, cols=h -> vt[(b*KH+kh)*H + h][t]
            int h = tid >> 1, half = tid & 1;
            int tglob = brow + p * 64 + half * 32;
            int b = tglob / T_, tloc = tglob % T_;
            __half* dstp = vdst + ((size_t)(b * KH_ + kh) * H_ + h) * T_ + tloc;
#pragma unroll
            for (int j = 0; j < 32; j++)
                dstp[j] = __float2half_rn(Cs[(half * 32 + j) * CST + h]);
        }
        __syncthreads();
    }
}

// ---------------------------------------------------------------------------
// FP16 tensor-core flash attention (exact R7 kernel)
// ---------------------------------------------------------------------------
#define KST  68
#define VSTW 68
#define PSTW 68
#define FA_SMEM ((2*128*KST + 2*128*VSTW + 8*16*PSTW) * 4)

__global__ __launch_bounds__(256, 1)
void flash16(const uint32_t* __restrict__ qh, const uint32_t* __restrict__ kk,
             const uint32_t* __restrict__ vt, uint32_t* __restrict__ o) {
    extern __shared__ uint32_t sm_u[];
    uint32_t* Ks = sm_u;
    uint32_t* Vs = Ks + 2 * 128 * KST;
    uint32_t* Ps = Vs + 2 * 128 * VSTW;

    int qt = (int)gridDim.x - 1 - (int)blockIdx.x;
    int n  = blockIdx.y;
    int b  = blockIdx.z;
    int khd = n >> 2;
    int tid = threadIdx.x, warp = tid >> 5, lane = tid & 31;
    int lr = lane >> 2, lc = lane & 3;
    int q0 = qt * 128;

    uint32_t qf[8][4];
#pragma unroll
    for (int pass = 0; pass < 2; pass++) {
#pragma unroll
        for (int u = 0; u < 4; u++) {
            int f = tid + 256 * u;
            int r = f >> 4, w4 = (f & 15) * 4;
            *(uint4*)(Ks + r * KST + w4) = *(const uint4*)(qh +
                ((size_t)((b * T_ + q0 + pass * 64 + r) * NH_ + n) << 6) + w4);
        }
        __syncthreads();
        if ((warp >> 2) == pass) {
            int mr = (warp & 3) * 16;
#pragma unroll
            for (int hs = 0; hs < 8; hs++) {
                const uint32_t* p = Ks + (mr + lr) * KST + hs * 8 + lc;
                qf[hs][0] = p[0];
                qf[hs][1] = p[8 * KST];
                qf[hs][2] = p[4];
                qf[hs][3] = p[8 * KST + 4];
            }
        }
        __syncthreads();
    }

    float m_[2] = {-1e30f, -1e30f};
    float l_[2] = {0.f, 0.f};
    float oacc[16][4];
#pragma unroll
    for (int ns = 0; ns < 16; ns++)
#pragma unroll
        for (int j = 0; j < 4; j++) oacc[ns][j] = 0.f;

    int row0 = q0 + warp * 16 + lr;
    int njt = qt + 1;

    auto load_kv = [&](int jt, int bufsel) {
        int s0 = jt * 128;
        uint32_t* Kd = Ks + bufsel * 128 * KST;
        uint32_t* Vd = Vs + bufsel * 128 * VSTW;
#pragma unroll
        for (int u = 0; u < 8; u++) {
            int f = tid + 256 * u;
            int r = f >> 4, w4 = (f & 15) * 4;
            cpasync16(Kd + r * KST + w4,
                      kk + ((size_t)((b * T_ + s0 + r) * KH_ + khd) << 6) + w4);
            cpasync16(Vd + r * VSTW + w4,
                      vt + ((((size_t)(b * KH_ + khd) * H_ + r) * T_ + s0) >> 1) + w4);
        }
    };

    load_kv(0, 0);
    asm volatile("cp.async.commit_group;\n");

    for (int jt = 0; jt < njt; jt++) {
        int buf = jt & 1;
        if (jt + 1 < njt) {
            load_kv(jt + 1, buf ^ 1);
            asm volatile("cp.async.commit_group;\n");
            asm volatile("cp.async.wait_group 1;\n");
        } else {
            asm volatile("cp.async.wait_group 0;\n");
        }
        __syncthreads();

        const uint32_t* Kb = Ks + buf * 128 * KST;
        const uint32_t* Vb = Vs + buf * 128 * VSTW;
        int s0 = jt * 128;

        float s_[16][4];
#pragma unroll
        for (int ns = 0; ns < 16; ns++)
#pragma unroll
            for (int j = 0; j < 4; j++) s_[ns][j] = 0.f;
#pragma unroll
        for (int hs = 0; hs < 8; hs++) {
#pragma unroll
            for (int ns = 0; ns < 16; ns++) {
                const uint32_t* p = Kb + (ns * 8 + lr) * KST + hs * 8 + lc;
                uint32_t bf[2] = {p[0], p[4]};
                mma16(s_[ns], qf[hs], bf);
            }
        }

        if (jt == qt) {
#pragma unroll
            for (int ns = 0; ns < 16; ns++) {
                int col = s0 + ns * 8 + 2 * lc;
                if (col > row0)     s_[ns][0] = -1e30f;
                if (col + 1 > row0) s_[ns][1] = -1e30f;
                if (col > row0 + 8)     s_[ns][2] = -1e30f;
                if (col + 1 > row0 + 8) s_[ns][3] = -1e30f;
            }
        }

        float mx0 = -1e30f, mx1 = -1e30f;
#pragma unroll
        for (int ns = 0; ns < 16; ns++) {
            mx0 = fmaxf(mx0, fmaxf(s_[ns][0], s_[ns][1]));
            mx1 = fmaxf(mx1, fmaxf(s_[ns][2], s_[ns][3]));
        }
        mx0 = fmaxf(mx0, __shfl_xor_sync(0xffffffffu, mx0, 1));
        mx0 = fmaxf(mx0, __shfl_xor_sync(0xffffffffu, mx0, 2));
        mx1 = fmaxf(mx1, __shfl_xor_sync(0xffffffffu, mx1, 1));
        mx1 = fmaxf(mx1, __shfl_xor_sync(0xffffffffu, mx1, 2));
        float mn0 = fmaxf(m_[0], mx0), mn1 = fmaxf(m_[1], mx1);
        float a0 = __expf(m_[0] - mn0), a1 = __expf(m_[1] - mn1);
        float sum0 = 0.f, sum1 = 0.f;
        uint32_t* Pw = Ps + warp * 16 * PSTW;
#pragma unroll
        for (int ns = 0; ns < 16; ns++) {
            float p0 = __expf(s_[ns][0] - mn0);
            float p1 = __expf(s_[ns][1] - mn0);
            float p2 = __expf(s_[ns][2] - mn1);
            float p3 = __expf(s_[ns][3] - mn1);
            sum0 += p0 + p1;
            sum1 += p2 + p3;
            Pw[lr * PSTW + ns * 4 + lc]       = f2h2(p0, p1);
            Pw[(lr + 8) * PSTW + ns * 4 + lc] = f2h2(p2, p3);
        }
        sum0 += __shfl_xor_sync(0xffffffffu, sum0, 1);
        sum0 += __shfl_xor_sync(0xffffffffu, sum0, 2);
        sum1 += __shfl_xor_sync(0xffffffffu, sum1, 1);
        sum1 += __shfl_xor_sync(0xffffffffu, sum1, 2);
        l_[0] = l_[0] * a0 + sum0;
        l_[1] = l_[1] * a1 + sum1;
        m_[0] = mn0; m_[1] = mn1;

#pragma unroll
        for (int ns = 0; ns < 16; ns++) {
            oacc[ns][0] *= a0; oacc[ns][1] *= a0;
            oacc[ns][2] *= a1; oacc[ns][3] *= a1;
        }
        __syncwarp();

#pragma unroll
        for (int ks = 0; ks < 8; ks++) {
            const uint32_t* pp = Pw + lr * PSTW + ks * 8 + lc;
            uint32_t af[4] = {pp[0], pp[8 * PSTW], pp[4], pp[8 * PSTW + 4]};
#pragma unroll
            for (int ns = 0; ns < 16; ns++) {
                const uint32_t* vp = Vb + (ns * 8 + lr) * VSTW + ks * 8 + lc;
                uint32_t bf[2] = {vp[0], vp[4]};
                mma16(oacc[ns], af, bf);
            }
        }
        __syncthreads();
    }

    float inv0 = 1.f / l_[0], inv1 = 1.f / l_[1];
    size_t wb0 = ((size_t)((b * T_ + row0) * NH_ + n) << 6);
    size_t wb1 = ((size_t)((b * T_ + row0 + 8) * NH_ + n) << 6);
#pragma unroll
    for (int ns = 0; ns < 16; ns++) {
        o[wb0 + ns * 4 + lc] = f2h2(oacc[ns][0] * inv0, oacc[ns][1] * inv0);
        o[wb1 + ns * 4 + lc] = f2h2(oacc[ns][2] * inv1, oacc[ns][3] * inv1);
    }
}

// ---------------------------------------------------------------------------
extern "C" void kernel_launch(void* const* d_in, const int* in_sizes, int n_in,
                              void* d_out, int out_size) {
    const float* Xq   = (const float*)d_in[0];
    const float* Xkv  = (const float*)d_in[1];
    const int*   qpos = (const int*)  d_in[2];
    const int*   kpos = (const int*)  d_in[3];
    const float* Wq   = (const float*)d_in[4];
    const float* Wk   = (const float*)d_in[5];
    const float* Wv   = (const float*)d_in[6];
    const float* Wo   = (const float*)d_in[7];
    float* out = (float*)d_out;

    __half *xqh, *xkvh, *wqt, *wkt, *wvt, *wot, *qh, *kh, *vt, *attn;
    float2 *scq, *sck;
    cudaGetSymbolAddress((void**)&xqh,  g_xqh);
    cudaGetSymbolAddress((void**)&xkvh, g_xkvh);
    cudaGetSymbolAddress((void**)&wqt,  g_wqt);
    cudaGetSymbolAddress((void**)&wkt,  g_wkt);
    cudaGetSymbolAddress((void**)&wvt,  g_wvt);
    cudaGetSymbolAddress((void**)&wot,  g_wot);
    cudaGetSymbolAddress((void**)&scq,  g_scq);
    cudaGetSymbolAddress((void**)&sck,  g_sck);
    cudaGetSymbolAddress((void**)&qh,   g_qh);
    cudaGetSymbolAddress((void**)&kh,   g_kh);
    cudaGetSymbolAddress((void**)&vt,   g_vt);
    cudaGetSymbolAddress((void**)&attn, g_attn);

    const int M = B_ * T_;  // 4096
    const int NHH = NH_ * H_, KHH = KH_ * H_;
    const float scale = 0.08838834764831845f; // 1/sqrt(128)

    // inputs -> fp16; weights -> fp16 transposed; rope tables
    cvt16<<<(B_*T_*D_) / 1024, 256>>>(Xq,  (__half2*)xqh);
    cvt16<<<(B_*T_*D_) / 1024, 256>>>(Xkv, (__half2*)xkvh);
    tr16<<<dim3(NHH / 32, D_ / 32), 256>>>(Wq, wqt, D_, NHH);
    tr16<<<dim3(KHH / 32, D_ / 32), 256>>>(Wk, wkt, D_, KHH);
    tr16<<<dim3(KHH / 32, D_ / 32), 256>>>(Wv, wvt, D_, KHH);
    tr16<<<dim3(D_ / 32, NHH / 32), 256>>>(Wo, wot, NHH, D_);
    ropetab<<<M, 64>>>(qpos, kpos, scq, sck);

    // projections with fused rope / V-transpose epilogues
    gemm16_qrope<<<dim3(NHH / 128, M / 128), 256>>>(
        (const uint32_t*)xqh, (const uint32_t*)wqt, qh, scq, D_, scale);
    gemm16_kvf<<<dim3(KHH / 128, M / 128, 2), 256>>>(
        (const uint32_t*)xkvh, (const uint32_t*)wkt, (const uint32_t*)wvt,
        kh, vt, sck, D_);

    // flash attention (fp16 mma.sync, KV tile 128)
    cudaFuncSetAttribute(flash16,
                         cudaFuncAttributeMaxDynamicSharedMemorySize, FA_SMEM);
    flash16<<<dim3(T_ / 128, NH_, B_), 256, FA_SMEM>>>(
        (const uint32_t*)qh, (const uint32_t*)kh, (const uint32_t*)vt,
        (uint32_t*)attn);

    // output projection
    gemm16<<<dim3(D_ / 128, M / 128), 256>>>(
        (const uint32_t*)attn, (const uint32_t*)wot, out, D_, NHH);
}

// round 13
// speedup vs baseline: 1.0491x; 1.0081x over previous
#include <cuda_runtime.h>
#include <cuda_fp16.h>
#include <math.h>
#include <stdint.h>

#define B_  2
#define T_  2048
#define D_  2048
#define NH_ 16
#define KH_ 4
#define H_  128

__device__ __half g_xqh [B_*T_*D_];
__device__ __half g_xkvh[B_*T_*D_];
__device__ __half g_wqt [NH_*H_*D_];
__device__ __half g_wkt [KH_*H_*D_];
__device__ __half g_wvt [KH_*H_*D_];
__device__ __half g_wot [D_*NH_*H_];
__device__ float2 g_scq [B_*T_*64];
__device__ float2 g_sck [B_*T_*64];
__device__ __half g_qh [B_*T_*NH_*H_];
__device__ __half g_kh [B_*T_*KH_*H_];
__device__ __half g_vt [B_*KH_*H_*T_];
__device__ __half g_attn[B_*T_*NH_*H_];

__device__ __forceinline__ uint32_t f2h2(float lo, float hi) {
    __half2 h = __floats2half2_rn(lo, hi);
    return *(uint32_t*)&h;
}

__device__ __forceinline__ float ex2f(float x) {
    float r;
    asm("ex2.approx.f32 %0, %1;" : "=f"(r) : "f"(x));
    return r;
}

__device__ __forceinline__ void cpasync16(void* dst, const void* src) {
    uint32_t d = (uint32_t)__cvta_generic_to_shared(dst);
    asm volatile("cp.async.cg.shared.global [%0], [%1], 16;\n" :: "r"(d), "l"(src));
}

__device__ __forceinline__ void mma16(float* c, const uint32_t* a, const uint32_t* b) {
    asm volatile(
        "mma.sync.aligned.m16n8k16.row.col.f32.f16.f16.f32 "
        "{%0,%1,%2,%3}, {%4,%5,%6,%7}, {%8,%9}, {%0,%1,%2,%3};\n"
        : "+f"(c[0]), "+f"(c[1]), "+f"(c[2]), "+f"(c[3])
        : "r"(a[0]), "r"(a[1]), "r"(a[2]), "r"(a[3]),
          "r"(b[0]), "r"(b[1]));
}

// ---------------------------------------------------------------------------
// Aux kernels
// ---------------------------------------------------------------------------
__global__ void cvt16_2(const float* __restrict__ s0, const float* __restrict__ s1,
                        __half2* __restrict__ d0, __half2* __restrict__ d1) {
    const float* s = blockIdx.z ? s1 : s0;
    __half2* d = blockIdx.z ? d1 : d0;
    int i = blockIdx.x * 256 + threadIdx.x;
    float4 a = ((const float4*)s)[i];
    d[2*i]   = __floats2half2_rn(a.x, a.y);
    d[2*i+1] = __floats2half2_rn(a.z, a.w);
}

__global__ void tr16(const float* __restrict__ src, __half* __restrict__ dst,
                     int R, int C) {
    __shared__ float tile[32][33];
    int c0 = blockIdx.x * 32, r0 = blockIdx.y * 32;
    int tx = threadIdx.x & 31, ty = threadIdx.x >> 5;
#pragma unroll
    for (int i = 0; i < 32; i += 8)
        tile[ty + i][tx] = src[(size_t)(r0 + ty + i) * C + c0 + tx];
    __syncthreads();
#pragma unroll
    for (int i = 0; i < 32; i += 8)
        dst[(size_t)(c0 + ty + i) * R + r0 + tx] = __float2half_rn(tile[tx][ty + i]);
}

__global__ void tr16_2(const float* __restrict__ s0, const float* __restrict__ s1,
                       __half* __restrict__ d0, __half* __restrict__ d1,
                       int R, int C) {
    __shared__ float tile[32][33];
    const float* src = blockIdx.z ? s1 : s0;
    __half* dst = blockIdx.z ? d1 : d0;
    int c0 = blockIdx.x * 32, r0 = blockIdx.y * 32;
    int tx = threadIdx.x & 31, ty = threadIdx.x >> 5;
#pragma unroll
    for (int i = 0; i < 32; i += 8)
        tile[ty + i][tx] = src[(size_t)(r0 + ty + i) * C + c0 + tx];
    __syncthreads();
#pragma unroll
    for (int i = 0; i < 32; i += 8)
        dst[(size_t)(c0 + ty + i) * R + r0 + tx] = __float2half_rn(tile[tx][ty + i]);
}

// sin/cos tables (exact double-precision math, as before)
__global__ void ropetab(const int* __restrict__ qpos, const int* __restrict__ kpos,
                        float2* __restrict__ scq, float2* __restrict__ sck) {
    int token = blockIdx.x;
    int i = threadIdx.x;  // 0..63
    double ts = exp(((double)i / 64.0) * 9.210340371976182736);
    double s_, c_;
    float angq = (float)qpos[token] / (float)ts;
    sincos((double)angq, &s_, &c_);
    scq[token * 64 + i] = make_float2((float)s_, (float)c_);
    float angk = (float)kpos[token] / (float)ts;
    sincos((double)angk, &s_, &c_);
    sck[token * 64 + i] = make_float2((float)s_, (float)c_);
}

// ---------------------------------------------------------------------------
// Shared fp16 GEMM mainloop (R7-verified)
// ---------------------------------------------------------------------------
#define GST 20
#define CST 133

__device__ __forceinline__
void gemm_mainloop(const uint32_t* __restrict__ A, const uint32_t* __restrict__ Bt,
                   int Kd, uint32_t* pool, float acc[4][4][4],
                   int brow, int bcol) {
    uint32_t* As = pool;
    uint32_t* Bs = pool + 5120;
    int tid  = threadIdx.x;
    int warp = tid >> 5, lane = tid & 31;
    int mw = (warp >> 2) * 64, nw = (warp & 3) * 32;
    int lr = lane >> 2, lc = lane & 3;
    int KW = Kd >> 1;

#pragma unroll
    for (int mi = 0; mi < 4; mi++)
#pragma unroll
        for (int ni = 0; ni < 4; ni++)
#pragma unroll
            for (int j = 0; j < 4; j++) acc[mi][ni][j] = 0.f;

    const int nkt = Kd >> 5;

    auto load_stage = [&](int kt, int buf) {
        int kw0 = kt * 16;
#pragma unroll
        for (int u = 0; u < 2; u++) {
            int c = tid + 256 * u;
            int row = c >> 2, w4 = (c & 3) * 4;
            cpasync16(&As[buf * 2560 + row * GST + w4],
                      &A[(size_t)(brow + row) * KW + kw0 + w4]);
            cpasync16(&Bs[buf * 2560 + row * GST + w4],
                      &Bt[(size_t)(bcol + row) * KW + kw0 + w4]);
        }
    };

    load_stage(0, 0);
    asm volatile("cp.async.commit_group;\n");

    for (int kt = 0; kt < nkt; kt++) {
        int buf = kt & 1;
        if (kt + 1 < nkt) {
            load_stage(kt + 1, buf ^ 1);
            asm volatile("cp.async.commit_group;\n");
            asm volatile("cp.async.wait_group 1;\n");
        } else {
            asm volatile("cp.async.wait_group 0;\n");
        }
        __syncthreads();

#pragma unroll
        for (int ks = 0; ks < 2; ks++) {
            uint32_t af[4][4], bf[4][2];
#pragma unroll
            for (int mi = 0; mi < 4; mi++) {
                const uint32_t* p = &As[buf * 2560 + (mw + mi * 16 + lr) * GST + ks * 8 + lc];
                af[mi][0] = p[0];
                af[mi][1] = p[8 * GST];
                af[mi][2] = p[4];
                af[mi][3] = p[8 * GST + 4];
            }
#pragma unroll
            for (int ni = 0; ni < 4; ni++) {
                const uint32_t* p = &Bs[buf * 2560 + (nw + ni * 8 + lr) * GST + ks * 8 + lc];
                bf[ni][0] = p[0];
                bf[ni][1] = p[4];
            }
#pragma unroll
            for (int mi = 0; mi < 4; mi++)
#pragma unroll
                for (int ni = 0; ni < 4; ni++)
                    mma16(acc[mi][ni], af[mi], bf[ni]);
        }
        __syncthreads();
    }
}

__device__ __forceinline__
void stage_pass(float* Cs, float acc[4][4][4], int p) {
    int tid = threadIdx.x, warp = tid >> 5, lane = tid & 31;
    int nw = (warp & 3) * 32;
    int lr = lane >> 2, lc = lane & 3;
    if ((warp >> 2) == p) {
#pragma unroll
        for (int mi = 0; mi < 4; mi++) {
#pragma unroll
            for (int ni = 0; ni < 4; ni++) {
                int r0 = mi * 16 + lr, cc = nw + ni * 8 + 2 * lc;
                Cs[r0 * CST + cc]           = acc[mi][ni][0];
                Cs[r0 * CST + cc + 1]       = acc[mi][ni][1];
                Cs[(r0 + 8) * CST + cc]     = acc[mi][ni][2];
                Cs[(r0 + 8) * CST + cc + 1] = acc[mi][ni][3];
            }
        }
    }
}

// ---------------------------------------------------------------------------
// Plain GEMM (output projection)
// ---------------------------------------------------------------------------
__global__ __launch_bounds__(256, 2)
void gemm16(const uint32_t* __restrict__ A, const uint32_t* __restrict__ Bt,
            float* __restrict__ C, int Nc, int Kd) {
    __shared__ uint32_t pool[10240];
    float acc[4][4][4];
    int brow = blockIdx.y * 128, bcol = blockIdx.x * 128;
    gemm_mainloop(A, Bt, Kd, pool, acc, brow, bcol);

    int tid = threadIdx.x, warp = tid >> 5, lane = tid & 31;
    int mw = (warp >> 2) * 64, nw = (warp & 3) * 32;
    int lr = lane >> 2, lc = lane & 3;
#pragma unroll
    for (int mi = 0; mi < 4; mi++) {
#pragma unroll
        for (int ni = 0; ni < 4; ni++) {
            int r0 = brow + mw + mi * 16 + lr;
            int cc = bcol + nw + ni * 8 + lc * 2;
            *(float2*)&C[(size_t)r0 * Nc + cc] =
                make_float2(acc[mi][ni][0], acc[mi][ni][1]);
            *(float2*)&C[(size_t)(r0 + 8) * Nc + cc] =
                make_float2(acc[mi][ni][2], acc[mi][ni][3]);
        }
    }
}

// ---------------------------------------------------------------------------
// Q projection + fused rope + scale (scale includes log2e for ex2 softmax)
// ---------------------------------------------------------------------------
__global__ __launch_bounds__(256, 2)
void gemm16_qrope(const uint32_t* __restrict__ A, const uint32_t* __restrict__ Bt,
                  __half* __restrict__ dst, const float2* __restrict__ sc,
                  int Kd, float scale) {
    __shared__ uint32_t pool[10240];
    float acc[4][4][4];
    int brow = blockIdx.y * 128, bcol = blockIdx.x * 128;
    gemm_mainloop(A, Bt, Kd, pool, acc, brow, bcol);

    float* Cs = (float*)pool;
    int tid = threadIdx.x;
    int n = bcol >> 7;
#pragma unroll
    for (int p = 0; p < 2; p++) {
        stage_pass(Cs, acc, p);
        __syncthreads();
        int row = tid >> 2, g = tid & 3;
        int token = brow + p * 64 + row;
        const float2* scrow = sc + (size_t)token * 64;
        __half* drow = dst + (((size_t)token * NH_ + n) << 7);
#pragma unroll
        for (int j = 0; j < 16; j++) {
            int i = g * 16 + j;
            float2 scv = scrow[i];
            float x1 = Cs[row * CST + i];
            float x2 = Cs[row * CST + i + 64];
            drow[i]      = __float2half_rn((x1 * scv.y - x2 * scv.x) * scale);
            drow[i + 64] = __float2half_rn((x2 * scv.y + x1 * scv.x) * scale);
        }
        __syncthreads();
    }
}

// ---------------------------------------------------------------------------
// K/V projection fused: z=0 K rope; z=1 V transpose
// ---------------------------------------------------------------------------
__global__ __launch_bounds__(256, 2)
void gemm16_kvf(const uint32_t* __restrict__ A,
                const uint32_t* __restrict__ B0, const uint32_t* __restrict__ B1,
                __half* __restrict__ kdst, __half* __restrict__ vdst,
                const float2* __restrict__ sc, int Kd) {
    __shared__ uint32_t pool[10240];
    float acc[4][4][4];
    int brow = blockIdx.y * 128, bcol = blockIdx.x * 128;
    int isv = blockIdx.z;
    gemm_mainloop(A, isv ? B1 : B0, Kd, pool, acc, brow, bcol);

    float* Cs = (float*)pool;
    int tid = threadIdx.x;
    int kh = bcol >> 7;
#pragma unroll
    for (int p = 0; p < 2; p++) {
        stage_pass(Cs, acc, p);
        __syncthreads();
        if (!isv) {
            int row = tid >> 2, g = tid & 3;
            int token = brow + p * 64 + row;
            const float2* scrow = sc + (size_t)token * 64;
            __half* drow = kdst + (((size_t)token * KH_ + kh) << 7);
#pragma unroll
            for (int j = 0; j < 16; j++) {
                int i = g * 16 + j;
                float2 scv = scrow[i];
                float x1 = Cs[row * CST + i];
                float x2 = Cs[row * CST + i + 64];
                drow[i]      = __float2half_rn(x1 * scv.y - x2 * scv.x);
                drow[i + 64] = __float2half_rn(x2 * scv.y + x1 * scv.x);
            }
        } else {
            int h = tid >> 1, half = tid & 1;
            int tglob = brow + p * 64 + half * 32;
            int b = tglob / T_, tloc = tglob % T_;
            __half* dstp = vdst + ((size_t)(b * KH_ + kh) * H_ + h) * T_ + tloc;
#pragma unroll
            for (int j = 0; j < 32; j++)
                dstp[j] = __float2half_rn(Cs[(half * 32 + j) * CST + h]);
        }
        __syncthreads();
    }
}

// ---------------------------------------------------------------------------
// FP16 flash attention (R7 core; softmax in base-2 domain, Q pre-scaled
// by scale*log2e, so p = ex2(s - m); mathematically identical softmax)
// ---------------------------------------------------------------------------
#define KST  68
#define VSTW 68
#define PSTW 68
#define FA_SMEM ((2*128*KST + 2*128*VSTW + 8*16*PSTW) * 4)

__global__ __launch_bounds__(256, 1)
void flash16(const uint32_t* __restrict__ qh, const uint32_t* __restrict__ kk,
             const uint32_t* __restrict__ vt, uint32_t* __restrict__ o) {
    extern __shared__ uint32_t sm_u[];
    uint32_t* Ks = sm_u;
    uint32_t* Vs = Ks + 2 * 128 * KST;
    uint32_t* Ps = Vs + 2 * 128 * VSTW;

    int qt = (int)gridDim.x - 1 - (int)blockIdx.x;
    int n  = blockIdx.y;
    int b  = blockIdx.z;
    int khd = n >> 2;
    int tid = threadIdx.x, warp = tid >> 5, lane = tid & 31;
    int lr = lane >> 2, lc = lane & 3;
    int q0 = qt * 128;

    uint32_t qf[8][4];
#pragma unroll
    for (int pass = 0; pass < 2; pass++) {
#pragma unroll
        for (int u = 0; u < 4; u++) {
            int f = tid + 256 * u;
            int r = f >> 4, w4 = (f & 15) * 4;
            *(uint4*)(Ks + r * KST + w4) = *(const uint4*)(qh +
                ((size_t)((b * T_ + q0 + pass * 64 + r) * NH_ + n) << 6) + w4);
        }
        __syncthreads();
        if ((warp >> 2) == pass) {
            int mr = (warp & 3) * 16;
#pragma unroll
            for (int hs = 0; hs < 8; hs++) {
                const uint32_t* p = Ks + (mr + lr) * KST + hs * 8 + lc;
                qf[hs][0] = p[0];
                qf[hs][1] = p[8 * KST];
                qf[hs][2] = p[4];
                qf[hs][3] = p[8 * KST + 4];
            }
        }
        __syncthreads();
    }

    float m_[2] = {-1e30f, -1e30f};
    float l_[2] = {0.f, 0.f};
    float oacc[16][4];
#pragma unroll
    for (int ns = 0; ns < 16; ns++)
#pragma unroll
        for (int j = 0; j < 4; j++) oacc[ns][j] = 0.f;

    int row0 = q0 + warp * 16 + lr;
    int njt = qt + 1;

    auto load_kv = [&](int jt, int bufsel) {
        int s0 = jt * 128;
        uint32_t* Kd = Ks + bufsel * 128 * KST;
        uint32_t* Vd = Vs + bufsel * 128 * VSTW;
#pragma unroll
        for (int u = 0; u < 8; u++) {
            int f = tid + 256 * u;
            int r = f >> 4, w4 = (f & 15) * 4;
            cpasync16(Kd + r * KST + w4,
                      kk + ((size_t)((b * T_ + s0 + r) * KH_ + khd) << 6) + w4);
            cpasync16(Vd + r * VSTW + w4,
                      vt + ((((size_t)(b * KH_ + khd) * H_ + r) * T_ + s0) >> 1) + w4);
        }
    };

    load_kv(0, 0);
    asm volatile("cp.async.commit_group;\n");

    for (int jt = 0; jt < njt; jt++) {
        int buf = jt & 1;
        if (jt + 1 < njt) {
            load_kv(jt + 1, buf ^ 1);
            asm volatile("cp.async.commit_group;\n");
            asm volatile("cp.async.wait_group 1;\n");
        } else {
            asm volatile("cp.async.wait_group 0;\n");
        }
        __syncthreads();

        const uint32_t* Kb = Ks + buf * 128 * KST;
        const uint32_t* Vb = Vs + buf * 128 * VSTW;
        int s0 = jt * 128;

        float s_[16][4];
#pragma unroll
        for (int ns = 0; ns < 16; ns++)
#pragma unroll
            for (int j = 0; j < 4; j++) s_[ns][j] = 0.f;
#pragma unroll
        for (int hs = 0; hs < 8; hs++) {
#pragma unroll
            for (int ns = 0; ns < 16; ns++) {
                const uint32_t* p = Kb + (ns * 8 + lr) * KST + hs * 8 + lc;
                uint32_t bf[2] = {p[0], p[4]};
                mma16(s_[ns], qf[hs], bf);
            }
        }

        if (jt == qt) {
#pragma unroll
            for (int ns = 0; ns < 16; ns++) {
                int col = s0 + ns * 8 + 2 * lc;
                if (col > row0)     s_[ns][0] = -1e30f;
                if (col + 1 > row0) s_[ns][1] = -1e30f;
                if (col > row0 + 8)     s_[ns][2] = -1e30f;
                if (col + 1 > row0 + 8) s_[ns][3] = -1e30f;
            }
        }

        float mx0 = -1e30f, mx1 = -1e30f;
#pragma unroll
        for (int ns = 0; ns < 16; ns++) {
            mx0 = fmaxf(mx0, fmaxf(s_[ns][0], s_[ns][1]));
            mx1 = fmaxf(mx1, fmaxf(s_[ns][2], s_[ns][3]));
        }
        mx0 = fmaxf(mx0, __shfl_xor_sync(0xffffffffu, mx0, 1));
        mx0 = fmaxf(mx0, __shfl_xor_sync(0xffffffffu, mx0, 2));
        mx1 = fmaxf(mx1, __shfl_xor_sync(0xffffffffu, mx1, 1));
        mx1 = fmaxf(mx1, __shfl_xor_sync(0xffffffffu, mx1, 2));
        float mn0 = fmaxf(m_[0], mx0), mn1 = fmaxf(m_[1], mx1);
        float a0 = ex2f(m_[0] - mn0), a1 = ex2f(m_[1] - mn1);
        float sum0 = 0.f, sum1 = 0.f;
        uint32_t* Pw = Ps + warp * 16 * PSTW;
#pragma unroll
        for (int ns = 0; ns < 16; ns++) {
            float p0 = ex2f(s_[ns][0] - mn0);
            float p1 = ex2f(s_[ns][1] - mn0);
            float p2 = ex2f(s_[ns][2] - mn1);
            float p3 = ex2f(s_[ns][3] - mn1);
            sum0 += p0 + p1;
            sum1 += p2 + p3;
            Pw[lr * PSTW + ns * 4 + lc]       = f2h2(p0, p1);
            Pw[(lr + 8) * PSTW + ns * 4 + lc] = f2h2(p2, p3);
        }
        sum0 += __shfl_xor_sync(0xffffffffu, sum0, 1);
        sum0 += __shfl_xor_sync(0xffffffffu, sum0, 2);
        sum1 += __shfl_xor_sync(0xffffffffu, sum1, 1);
        sum1 += __shfl_xor_sync(0xffffffffu, sum1, 2);
        l_[0] = l_[0] * a0 + sum0;
        l_[1] = l_[1] * a1 + sum1;
        m_[0] = mn0; m_[1] = mn1;

#pragma unroll
        for (int ns = 0; ns < 16; ns++) {
            oacc[ns][0] *= a0; oacc[ns][1] *= a0;
            oacc[ns][2] *= a1; oacc[ns][3] *= a1;
        }
        __syncwarp();

#pragma unroll
        for (int ks = 0; ks < 8; ks++) {
            const uint32_t* pp = Pw + lr * PSTW + ks * 8 + lc;
            uint32_t af[4] = {pp[0], pp[8 * PSTW], pp[4], pp[8 * PSTW + 4]};
#pragma unroll
            for (int ns = 0; ns < 16; ns++) {
                const uint32_t* vp = Vb + (ns * 8 + lr) * VSTW + ks * 8 + lc;
                uint32_t bf[2] = {vp[0], vp[4]};
                mma16(oacc[ns], af, bf);
            }
        }
        __syncthreads();
    }

    float inv0 = 1.f / l_[0], inv1 = 1.f / l_[1];
    size_t wb0 = ((size_t)((b * T_ + row0) * NH_ + n) << 6);
    size_t wb1 = ((size_t)((b * T_ + row0 + 8) * NH_ + n) << 6);
#pragma unroll
    for (int ns = 0; ns < 16; ns++) {
        o[wb0 + ns * 4 + lc] = f2h2(oacc[ns][0] * inv0, oacc[ns][1] * inv0);
        o[wb1 + ns * 4 + lc] = f2h2(oacc[ns][2] * inv1, oacc[ns][3] * inv1);
    }
}

// ---------------------------------------------------------------------------
extern "C" void kernel_launch(void* const* d_in, const int* in_sizes, int n_in,
                              void* d_out, int out_size) {
    const float* Xq   = (const float*)d_in[0];
    const float* Xkv  = (const float*)d_in[1];
    const int*   qpos = (const int*)  d_in[2];
    const int*   kpos = (const int*)  d_in[3];
    const float* Wq   = (const float*)d_in[4];
    const float* Wk   = (const float*)d_in[5];
    const float* Wv   = (const float*)d_in[6];
    const float* Wo   = (const float*)d_in[7];
    float* out = (float*)d_out;

    __half *xqh, *xkvh, *wqt, *wkt, *wvt, *wot, *qh, *kh, *vt, *attn;
    float2 *scq, *sck;
    cudaGetSymbolAddress((void**)&xqh,  g_xqh);
    cudaGetSymbolAddress((void**)&xkvh, g_xkvh);
    cudaGetSymbolAddress((void**)&wqt,  g_wqt);
    cudaGetSymbolAddress((void**)&wkt,  g_wkt);
    cudaGetSymbolAddress((void**)&wvt,  g_wvt);
    cudaGetSymbolAddress((void**)&wot,  g_wot);
    cudaGetSymbolAddress((void**)&scq,  g_scq);
    cudaGetSymbolAddress((void**)&sck,  g_sck);
    cudaGetSymbolAddress((void**)&qh,   g_qh);
    cudaGetSymbolAddress((void**)&kh,   g_kh);
    cudaGetSymbolAddress((void**)&vt,   g_vt);
    cudaGetSymbolAddress((void**)&attn, g_attn);

    const int M = B_ * T_;  // 4096
    const int NHH = NH_ * H_, KHH = KH_ * H_;
    // 1/sqrt(128) * log2(e): softmax runs in base-2 domain
    const float scale = 0.08838834764831845f * 1.4426950408889634f;

    cvt16_2<<<dim3((B_*T_*D_) / 1024, 1, 2), 256>>>(
        Xq, Xkv, (__half2*)xqh, (__half2*)xkvh);
    tr16<<<dim3(NHH / 32, D_ / 32), 256>>>(Wq, wqt, D_, NHH);
    tr16_2<<<dim3(KHH / 32, D_ / 32, 2), 256>>>(Wk, Wv, wkt, wvt, D_, KHH);
    tr16<<<dim3(D_ / 32, NHH / 32), 256>>>(Wo, wot, NHH, D_);
    ropetab<<<M, 64>>>(qpos, kpos, scq, sck);

    gemm16_qrope<<<dim3(NHH / 128, M / 128), 256>>>(
        (const uint32_t*)xqh, (const uint32_t*)wqt, qh, scq, D_, scale);
    gemm16_kvf<<<dim3(KHH / 128, M / 128, 2), 256>>>(
        (const uint32_t*)xkvh, (const uint32_t*)wkt, (const uint32_t*)wvt,
        kh, vt, sck, D_);

    cudaFuncSetAttribute(flash16,
                         cudaFuncAttributeMaxDynamicSharedMemorySize, FA_SMEM);
    flash16<<<dim3(T_ / 128, NH_, B_), 256, FA_SMEM>>>(
        (const uint32_t*)qh, (const uint32_t*)kh, (const uint32_t*)vt,
        (uint32_t*)attn);

    gemm16<<<dim3(D_ / 128, M / 128), 256>>>(
        (const uint32_t*)attn, (const uint32_t*)wot, out, D_, NHH);
}

// round 14
// speedup vs baseline: 1.0671x; 1.0172x over previous
#include <cuda_runtime.h>
#include <cuda_fp16.h>
#include <math.h>
#include <stdint.h>

#define B_  2
#define T_  2048
#define D_  2048
#define NH_ 16
#define KH_ 4
#define H_  128

__device__ __half g_xqh [B_*T_*D_];
__device__ __half g_xkvh[B_*T_*D_];
__device__ __half g_wqt [NH_*H_*D_];
__device__ __half g_wkt [KH_*H_*D_];
__device__ __half g_wvt [KH_*H_*D_];
__device__ __half g_wot [D_*NH_*H_];
__device__ float2 g_scq [B_*T_*64];
__device__ float2 g_sck [B_*T_*64];
__device__ __half g_qh [B_*T_*NH_*H_];
__device__ __half g_kh [B_*T_*KH_*H_];
__device__ __half g_vt [B_*KH_*H_*T_];
__device__ __half g_attn[B_*T_*NH_*H_];

__device__ __forceinline__ uint32_t f2h2(float lo, float hi) {
    __half2 h = __floats2half2_rn(lo, hi);
    return *(uint32_t*)&h;
}

__device__ __forceinline__ float ex2f(float x) {
    float r;
    asm("ex2.approx.f32 %0, %1;" : "=f"(r) : "f"(x));
    return r;
}

__device__ __forceinline__ void cpasync16(void* dst, const void* src) {
    uint32_t d = (uint32_t)__cvta_generic_to_shared(dst);
    asm volatile("cp.async.cg.shared.global [%0], [%1], 16;\n" :: "r"(d), "l"(src));
}

__device__ __forceinline__ void mma16(float* c, const uint32_t* a, const uint32_t* b) {
    asm volatile(
        "mma.sync.aligned.m16n8k16.row.col.f32.f16.f16.f32 "
        "{%0,%1,%2,%3}, {%4,%5,%6,%7}, {%8,%9}, {%0,%1,%2,%3};\n"
        : "+f"(c[0]), "+f"(c[1]), "+f"(c[2]), "+f"(c[3])
        : "r"(a[0]), "r"(a[1]), "r"(a[2]), "r"(a[3]),
          "r"(b[0]), "r"(b[1]));
}

// ---------------------------------------------------------------------------
// PREP: one launch does cvt(Xq), cvt(Xkv), tr(Wq), tr(Wk), tr(Wv), tr(Wo),
// rope sin/cos tables. 1D grid with range decode.
// ---------------------------------------------------------------------------
#define NCVT  ((B_*T_*D_) / 1024)              // 8192 per input
#define TQ_   ((NH_*H_/32) * (D_/32))          // 4096
#define TK_   ((KH_*H_/32) * (D_/32))          // 1024
#define TO_   ((D_/32) * (NH_*H_/32))          // 4096
#define NROPE ((B_*T_) / 4)                    // 1024
#define PREP_GRID (2*NCVT + TQ_ + 2*TK_ + TO_ + NROPE)

__device__ __forceinline__
void tr_tile(const float* __restrict__ src, __half* __restrict__ dst,
             int R, int C, int c0, int r0, float (*tile)[33]) {
    int tx = threadIdx.x & 31, ty = threadIdx.x >> 5;
#pragma unroll
    for (int i = 0; i < 32; i += 8)
        tile[ty + i][tx] = src[(size_t)(r0 + ty + i) * C + c0 + tx];
    __syncthreads();
#pragma unroll
    for (int i = 0; i < 32; i += 8)
        dst[(size_t)(c0 + ty + i) * R + r0 + tx] = __float2half_rn(tile[tx][ty + i]);
}

__global__ void prep(const float* __restrict__ Xq, const float* __restrict__ Xkv,
                     __half2* __restrict__ xqh, __half2* __restrict__ xkvh,
                     const float* __restrict__ Wq, const float* __restrict__ Wk,
                     const float* __restrict__ Wv, const float* __restrict__ Wo,
                     __half* __restrict__ wqt, __half* __restrict__ wkt,
                     __half* __restrict__ wvt, __half* __restrict__ wot,
                     const int* __restrict__ qpos, const int* __restrict__ kpos,
                     float2* __restrict__ scq, float2* __restrict__ sck) {
    __shared__ float tile[32][33];
    int bid = blockIdx.x, tid = threadIdx.x;

    if (bid < 2 * NCVT) {                                    // input cvt
        const float* s = (bid < NCVT) ? Xq : Xkv;
        __half2* d = (bid < NCVT) ? xqh : xkvh;
        int i = (bid % NCVT) * 256 + tid;
        float4 a = ((const float4*)s)[i];
        d[2*i]   = __floats2half2_rn(a.x, a.y);
        d[2*i+1] = __floats2half2_rn(a.z, a.w);
        return;
    }
    bid -= 2 * NCVT;
    if (bid < TQ_) {                                          // Wq^T
        int nx = NH_ * H_ / 32;
        tr_tile(Wq, wqt, D_, NH_*H_, (bid % nx) * 32, (bid / nx) * 32, tile);
        return;
    }
    bid -= TQ_;
    if (bid < 2 * TK_) {                                      // Wk^T / Wv^T
        const float* s = (bid < TK_) ? Wk : Wv;
        __half* d = (bid < TK_) ? wkt : wvt;
        int r = bid % TK_, nx = KH_ * H_ / 32;
        tr_tile(s, d, D_, KH_*H_, (r % nx) * 32, (r / nx) * 32, tile);
        return;
    }
    bid -= 2 * TK_;
    if (bid < TO_) {                                          // Wo^T
        int nx = D_ / 32;
        tr_tile(Wo, wot, NH_*H_, D_, (bid % nx) * 32, (bid / nx) * 32, tile);
        return;
    }
    bid -= TO_;
    {                                                         // rope tables
        int token = bid * 4 + (tid >> 6);
        int i = tid & 63;
        double ts = exp(((double)i / 64.0) * 9.210340371976182736);
        double s_, c_;
        float angq = (float)qpos[token] / (float)ts;
        sincos((double)angq, &s_, &c_);
        scq[token * 64 + i] = make_float2((float)s_, (float)c_);
        float angk = (float)kpos[token] / (float)ts;
        sincos((double)angk, &s_, &c_);
        sck[token * 64 + i] = make_float2((float)s_, (float)c_);
    }
}

// ---------------------------------------------------------------------------
// Shared fp16 GEMM mainloop (R7-verified)
// ---------------------------------------------------------------------------
#define GST 20
#define CST 133

__device__ __forceinline__
void gemm_mainloop(const uint32_t* __restrict__ A, const uint32_t* __restrict__ Bt,
                   int Kd, uint32_t* pool, float acc[4][4][4],
                   int brow, int bcol) {
    uint32_t* As = pool;
    uint32_t* Bs = pool + 5120;
    int tid  = threadIdx.x;
    int warp = tid >> 5, lane = tid & 31;
    int mw = (warp >> 2) * 64, nw = (warp & 3) * 32;
    int lr = lane >> 2, lc = lane & 3;
    int KW = Kd >> 1;

#pragma unroll
    for (int mi = 0; mi < 4; mi++)
#pragma unroll
        for (int ni = 0; ni < 4; ni++)
#pragma unroll
            for (int j = 0; j < 4; j++) acc[mi][ni][j] = 0.f;

    const int nkt = Kd >> 5;

    auto load_stage = [&](int kt, int buf) {
        int kw0 = kt * 16;
#pragma unroll
        for (int u = 0; u < 2; u++) {
            int c = tid + 256 * u;
            int row = c >> 2, w4 = (c & 3) * 4;
            cpasync16(&As[buf * 2560 + row * GST + w4],
                      &A[(size_t)(brow + row) * KW + kw0 + w4]);
            cpasync16(&Bs[buf * 2560 + row * GST + w4],
                      &Bt[(size_t)(bcol + row) * KW + kw0 + w4]);
        }
    };

    load_stage(0, 0);
    asm volatile("cp.async.commit_group;\n");

    for (int kt = 0; kt < nkt; kt++) {
        int buf = kt & 1;
        if (kt + 1 < nkt) {
            load_stage(kt + 1, buf ^ 1);
            asm volatile("cp.async.commit_group;\n");
            asm volatile("cp.async.wait_group 1;\n");
        } else {
            asm volatile("cp.async.wait_group 0;\n");
        }
        __syncthreads();

#pragma unroll
        for (int ks = 0; ks < 2; ks++) {
            uint32_t af[4][4], bf[4][2];
#pragma unroll
            for (int mi = 0; mi < 4; mi++) {
                const uint32_t* p = &As[buf * 2560 + (mw + mi * 16 + lr) * GST + ks * 8 + lc];
                af[mi][0] = p[0];
                af[mi][1] = p[8 * GST];
                af[mi][2] = p[4];
                af[mi][3] = p[8 * GST + 4];
            }
#pragma unroll
            for (int ni = 0; ni < 4; ni++) {
                const uint32_t* p = &Bs[buf * 2560 + (nw + ni * 8 + lr) * GST + ks * 8 + lc];
                bf[ni][0] = p[0];
                bf[ni][1] = p[4];
            }
#pragma unroll
            for (int mi = 0; mi < 4; mi++)
#pragma unroll
                for (int ni = 0; ni < 4; ni++)
                    mma16(acc[mi][ni], af[mi], bf[ni]);
        }
        __syncthreads();
    }
}

__device__ __forceinline__
void stage_pass(float* Cs, float acc[4][4][4], int p) {
    int tid = threadIdx.x, warp = tid >> 5, lane = tid & 31;
    int nw = (warp & 3) * 32;
    int lr = lane >> 2, lc = lane & 3;
    if ((warp >> 2) == p) {
#pragma unroll
        for (int mi = 0; mi < 4; mi++) {
#pragma unroll
            for (int ni = 0; ni < 4; ni++) {
                int r0 = mi * 16 + lr, cc = nw + ni * 8 + 2 * lc;
                Cs[r0 * CST + cc]           = acc[mi][ni][0];
                Cs[r0 * CST + cc + 1]       = acc[mi][ni][1];
                Cs[(r0 + 8) * CST + cc]     = acc[mi][ni][2];
                Cs[(r0 + 8) * CST + cc + 1] = acc[mi][ni][3];
            }
        }
    }
}

// ---------------------------------------------------------------------------
// PROJ_ALL: one launch. bid<512: Q-proj+rope; <640: K-proj+rope; <768: V-proj+T
// ---------------------------------------------------------------------------
__global__ __launch_bounds__(256, 2)
void proj_all(const uint32_t* __restrict__ xqh, const uint32_t* __restrict__ xkvh,
              const uint32_t* __restrict__ wqt, const uint32_t* __restrict__ wkt,
              const uint32_t* __restrict__ wvt,
              __half* __restrict__ qdst, __half* __restrict__ kdst,
              __half* __restrict__ vdst,
              const float2* __restrict__ scq, const float2* __restrict__ sck,
              float scale) {
    __shared__ uint32_t pool[10240];
    float acc[4][4][4];
    int bid = blockIdx.x, tid = threadIdx.x;
    float* Cs = (float*)pool;

    if (bid < 512) {
        // -------- Q projection + rope + scale --------
        int n = bid & 15, brow = (bid >> 4) * 128;
        gemm_mainloop(xqh, wqt, D_, pool, acc, brow, n * 128);
#pragma unroll
        for (int p = 0; p < 2; p++) {
            stage_pass(Cs, acc, p);
            __syncthreads();
            int row = tid >> 2, g = tid & 3;
            int token = brow + p * 64 + row;
            const float2* scrow = scq + (size_t)token * 64;
            __half* drow = qdst + (((size_t)token * NH_ + n) << 7);
#pragma unroll
            for (int j = 0; j < 16; j++) {
                int i = g * 16 + j;
                float2 scv = scrow[i];
                float x1 = Cs[row * CST + i];
                float x2 = Cs[row * CST + i + 64];
                drow[i]      = __float2half_rn((x1 * scv.y - x2 * scv.x) * scale);
                drow[i + 64] = __float2half_rn((x2 * scv.y + x1 * scv.x) * scale);
            }
            __syncthreads();
        }
    } else if (bid < 640) {
        // -------- K projection + rope --------
        int r = bid - 512;
        int kh = r & 3, brow = (r >> 2) * 128;
        gemm_mainloop(xkvh, wkt, D_, pool, acc, brow, kh * 128);
#pragma unroll
        for (int p = 0; p < 2; p++) {
            stage_pass(Cs, acc, p);
            __syncthreads();
            int row = tid >> 2, g = tid & 3;
            int token = brow + p * 64 + row;
            const float2* scrow = sck + (size_t)token * 64;
            __half* drow = kdst + (((size_t)token * KH_ + kh) << 7);
#pragma unroll
            for (int j = 0; j < 16; j++) {
                int i = g * 16 + j;
                float2 scv = scrow[i];
                float x1 = Cs[row * CST + i];
                float x2 = Cs[row * CST + i + 64];
                drow[i]      = __float2half_rn(x1 * scv.y - x2 * scv.x);
                drow[i + 64] = __float2half_rn(x2 * scv.y + x1 * scv.x);
            }
            __syncthreads();
        }
    } else {
        // -------- V projection + transpose --------
        int r = bid - 640;
        int kh = r & 3, brow = (r >> 2) * 128;
        gemm_mainloop(xkvh, wvt, D_, pool, acc, brow, kh * 128);
#pragma unroll
        for (int p = 0; p < 2; p++) {
            stage_pass(Cs, acc, p);
            __syncthreads();
            int h = tid >> 1, half = tid & 1;
            int tglob = brow + p * 64 + half * 32;
            int b = tglob / T_, tloc = tglob % T_;
            __half* dstp = vdst + ((size_t)(b * KH_ + kh) * H_ + h) * T_ + tloc;
#pragma unroll
            for (int j = 0; j < 32; j++)
                dstp[j] = __float2half_rn(Cs[(half * 32 + j) * CST + h]);
            __syncthreads();
        }
    }
}

// ---------------------------------------------------------------------------
// Plain GEMM (output projection)
// ---------------------------------------------------------------------------
__global__ __launch_bounds__(256, 2)
void gemm16(const uint32_t* __restrict__ A, const uint32_t* __restrict__ Bt,
            float* __restrict__ C, int Nc, int Kd) {
    __shared__ uint32_t pool[10240];
    float acc[4][4][4];
    int brow = blockIdx.y * 128, bcol = blockIdx.x * 128;
    gemm_mainloop(A, Bt, Kd, pool, acc, brow, bcol);

    int tid = threadIdx.x, warp = tid >> 5, lane = tid & 31;
    int mw = (warp >> 2) * 64, nw = (warp & 3) * 32;
    int lr = lane >> 2, lc = lane & 3;
#pragma unroll
    for (int mi = 0; mi < 4; mi++) {
#pragma unroll
        for (int ni = 0; ni < 4; ni++) {
            int r0 = brow + mw + mi * 16 + lr;
            int cc = bcol + nw + ni * 8 + lc * 2;
            *(float2*)&C[(size_t)r0 * Nc + cc] =
                make_float2(acc[mi][ni][0], acc[mi][ni][1]);
            *(float2*)&C[(size_t)(r0 + 8) * Nc + cc] =
                make_float2(acc[mi][ni][2], acc[mi][ni][3]);
        }
    }
}

// ---------------------------------------------------------------------------
// FP16 flash attention (R13: base-2 softmax, Q pre-scaled by scale*log2e)
// ---------------------------------------------------------------------------
#define KST  68
#define VSTW 68
#define PSTW 68
#define FA_SMEM ((2*128*KST + 2*128*VSTW + 8*16*PSTW) * 4)

__global__ __launch_bounds__(256, 1)
void flash16(const uint32_t* __restrict__ qh, const uint32_t* __restrict__ kk,
             const uint32_t* __restrict__ vt, uint32_t* __restrict__ o) {
    extern __shared__ uint32_t sm_u[];
    uint32_t* Ks = sm_u;
    uint32_t* Vs = Ks + 2 * 128 * KST;
    uint32_t* Ps = Vs + 2 * 128 * VSTW;

    int qt = (int)gridDim.x - 1 - (int)blockIdx.x;
    int n  = blockIdx.y;
    int b  = blockIdx.z;
    int khd = n >> 2;
    int tid = threadIdx.x, warp = tid >> 5, lane = tid & 31;
    int lr = lane >> 2, lc = lane & 3;
    int q0 = qt * 128;

    uint32_t qf[8][4];
#pragma unroll
    for (int pass = 0; pass < 2; pass++) {
#pragma unroll
        for (int u = 0; u < 4; u++) {
            int f = tid + 256 * u;
            int r = f >> 4, w4 = (f & 15) * 4;
            *(uint4*)(Ks + r * KST + w4) = *(const uint4*)(qh +
                ((size_t)((b * T_ + q0 + pass * 64 + r) * NH_ + n) << 6) + w4);
        }
        __syncthreads();
        if ((warp >> 2) == pass) {
            int mr = (warp & 3) * 16;
#pragma unroll
            for (int hs = 0; hs < 8; hs++) {
                const uint32_t* p = Ks + (mr + lr) * KST + hs * 8 + lc;
                qf[hs][0] = p[0];
                qf[hs][1] = p[8 * KST];
                qf[hs][2] = p[4];
                qf[hs][3] = p[8 * KST + 4];
            }
        }
        __syncthreads();
    }

    float m_[2] = {-1e30f, -1e30f};
    float l_[2] = {0.f, 0.f};
    float oacc[16][4];
#pragma unroll
    for (int ns = 0; ns < 16; ns++)
#pragma unroll
        for (int j = 0; j < 4; j++) oacc[ns][j] = 0.f;

    int row0 = q0 + warp * 16 + lr;
    int njt = qt + 1;

    auto load_kv = [&](int jt, int bufsel) {
        int s0 = jt * 128;
        uint32_t* Kd = Ks + bufsel * 128 * KST;
        uint32_t* Vd = Vs + bufsel * 128 * VSTW;
#pragma unroll
        for (int u = 0; u < 8; u++) {
            int f = tid + 256 * u;
            int r = f >> 4, w4 = (f & 15) * 4;
            cpasync16(Kd + r * KST + w4,
                      kk + ((size_t)((b * T_ + s0 + r) * KH_ + khd) << 6) + w4);
            cpasync16(Vd + r * VSTW + w4,
                      vt + ((((size_t)(b * KH_ + khd) * H_ + r) * T_ + s0) >> 1) + w4);
        }
    };

    load_kv(0, 0);
    asm volatile("cp.async.commit_group;\n");

    for (int jt = 0; jt < njt; jt++) {
        int buf = jt & 1;
        if (jt + 1 < njt) {
            load_kv(jt + 1, buf ^ 1);
            asm volatile("cp.async.commit_group;\n");
            asm volatile("cp.async.wait_group 1;\n");
        } else {
            asm volatile("cp.async.wait_group 0;\n");
        }
        __syncthreads();

        const uint32_t* Kb = Ks + buf * 128 * KST;
        const uint32_t* Vb = Vs + buf * 128 * VSTW;
        int s0 = jt * 128;

        float s_[16][4];
#pragma unroll
        for (int ns = 0; ns < 16; ns++)
#pragma unroll
            for (int j = 0; j < 4; j++) s_[ns][j] = 0.f;
#pragma unroll
        for (int hs = 0; hs < 8; hs++) {
#pragma unroll
            for (int ns = 0; ns < 16; ns++) {
                const uint32_t* p = Kb + (ns * 8 + lr) * KST + hs * 8 + lc;
                uint32_t bf[2] = {p[0], p[4]};
                mma16(s_[ns], qf[hs], bf);
            }
        }

        if (jt == qt) {
#pragma unroll
            for (int ns = 0; ns < 16; ns++) {
                int col = s0 + ns * 8 + 2 * lc;
                if (col > row0)     s_[ns][0] = -1e30f;
                if (col + 1 > row0) s_[ns][1] = -1e30f;
                if (col > row0 + 8)     s_[ns][2] = -1e30f;
                if (col + 1 > row0 + 8) s_[ns][3] = -1e30f;
            }
        }

        float mx0 = -1e30f, mx1 = -1e30f;
#pragma unroll
        for (int ns = 0; ns < 16; ns++) {
            mx0 = fmaxf(mx0, fmaxf(s_[ns][0], s_[ns][1]));
            mx1 = fmaxf(mx1, fmaxf(s_[ns][2], s_[ns][3]));
        }
        mx0 = fmaxf(mx0, __shfl_xor_sync(0xffffffffu, mx0, 1));
        mx0 = fmaxf(mx0, __shfl_xor_sync(0xffffffffu, mx0, 2));
        mx1 = fmaxf(mx1, __shfl_xor_sync(0xffffffffu, mx1, 1));
        mx1 = fmaxf(mx1, __shfl_xor_sync(0xffffffffu, mx1, 2));
        float mn0 = fmaxf(m_[0], mx0), mn1 = fmaxf(m_[1], mx1);
        float a0 = ex2f(m_[0] - mn0), a1 = ex2f(m_[1] - mn1);
        float sum0 = 0.f, sum1 = 0.f;
        uint32_t* Pw = Ps + warp * 16 * PSTW;
#pragma unroll
        for (int ns = 0; ns < 16; ns++) {
            float p0 = ex2f(s_[ns][0] - mn0);
            float p1 = ex2f(s_[ns][1] - mn0);
            float p2 = ex2f(s_[ns][2] - mn1);
            float p3 = ex2f(s_[ns][3] - mn1);
            sum0 += p0 + p1;
            sum1 += p2 + p3;
            Pw[lr * PSTW + ns * 4 + lc]       = f2h2(p0, p1);
            Pw[(lr + 8) * PSTW + ns * 4 + lc] = f2h2(p2, p3);
        }
        sum0 += __shfl_xor_sync(0xffffffffu, sum0, 1);
        sum0 += __shfl_xor_sync(0xffffffffu, sum0, 2);
        sum1 += __shfl_xor_sync(0xffffffffu, sum1, 1);
        sum1 += __shfl_xor_sync(0xffffffffu, sum1, 2);
        l_[0] = l_[0] * a0 + sum0;
        l_[1] = l_[1] * a1 + sum1;
        m_[0] = mn0; m_[1] = mn1;

#pragma unroll
        for (int ns = 0; ns < 16; ns++) {
            oacc[ns][0] *= a0; oacc[ns][1] *= a0;
            oacc[ns][2] *= a1; oacc[ns][3] *= a1;
        }
        __syncwarp();

#pragma unroll
        for (int ks = 0; ks < 8; ks++) {
            const uint32_t* pp = Pw + lr * PSTW + ks * 8 + lc;
            uint32_t af[4] = {pp[0], pp[8 * PSTW], pp[4], pp[8 * PSTW + 4]};
#pragma unroll
            for (int ns = 0; ns < 16; ns++) {
                const uint32_t* vp = Vb + (ns * 8 + lr) * VSTW + ks * 8 + lc;
                uint32_t bf[2] = {vp[0], vp[4]};
                mma16(oacc[ns], af, bf);
            }
        }
        __syncthreads();
    }

    float inv0 = 1.f / l_[0], inv1 = 1.f / l_[1];
    size_t wb0 = ((size_t)((b * T_ + row0) * NH_ + n) << 6);
    size_t wb1 = ((size_t)((b * T_ + row0 + 8) * NH_ + n) << 6);
#pragma unroll
    for (int ns = 0; ns < 16; ns++) {
        o[wb0 + ns * 4 + lc] = f2h2(oacc[ns][0] * inv0, oacc[ns][1] * inv0);
        o[wb1 + ns * 4 + lc] = f2h2(oacc[ns][2] * inv1, oacc[ns][3] * inv1);
    }
}

// ---------------------------------------------------------------------------
extern "C" void kernel_launch(void* const* d_in, const int* in_sizes, int n_in,
                              void* d_out, int out_size) {
    const float* Xq   = (const float*)d_in[0];
    const float* Xkv  = (const float*)d_in[1];
    const int*   qpos = (const int*)  d_in[2];
    const int*   kpos = (const int*)  d_in[3];
    const float* Wq   = (const float*)d_in[4];
    const float* Wk   = (const float*)d_in[5];
    const float* Wv   = (const float*)d_in[6];
    const float* Wo   = (const float*)d_in[7];
    float* out = (float*)d_out;

    __half *xqh, *xkvh, *wqt, *wkt, *wvt, *wot, *qh, *kh, *vt, *attn;
    float2 *scq, *sck;
    cudaGetSymbolAddress((void**)&xqh,  g_xqh);
    cudaGetSymbolAddress((void**)&xkvh, g_xkvh);
    cudaGetSymbolAddress((void**)&wqt,  g_wqt);
    cudaGetSymbolAddress((void**)&wkt,  g_wkt);
    cudaGetSymbolAddress((void**)&wvt,  g_wvt);
    cudaGetSymbolAddress((void**)&wot,  g_wot);
    cudaGetSymbolAddress((void**)&scq,  g_scq);
    cudaGetSymbolAddress((void**)&sck,  g_sck);
    cudaGetSymbolAddress((void**)&qh,   g_qh);
    cudaGetSymbolAddress((void**)&kh,   g_kh);
    cudaGetSymbolAddress((void**)&vt,   g_vt);
    cudaGetSymbolAddress((void**)&attn, g_attn);

    const int M = B_ * T_;  // 4096
    const int NHH = NH_ * H_;
    const float scale = 0.08838834764831845f * 1.4426950408889634f;

    // one prep launch: cvt inputs, transpose weights, rope tables
    prep<<<PREP_GRID, 256>>>(Xq, Xkv, (__half2*)xqh, (__half2*)xkvh,
                             Wq, Wk, Wv, Wo, wqt, wkt, wvt, wot,
                             qpos, kpos, scq, sck);

    // one projection launch: Q(+rope), K(+rope), V(+transpose)
    proj_all<<<768, 256>>>(
        (const uint32_t*)xqh, (const uint32_t*)xkvh,
        (const uint32_t*)wqt, (const uint32_t*)wkt, (const uint32_t*)wvt,
        qh, kh, vt, scq, sck, scale);

    // flash attention
    cudaFuncSetAttribute(flash16,
                         cudaFuncAttributeMaxDynamicSharedMemorySize, FA_SMEM);
    flash16<<<dim3(T_ / 128, NH_, B_), 256, FA_SMEM>>>(
        (const uint32_t*)qh, (const uint32_t*)kh, (const uint32_t*)vt,
        (uint32_t*)attn);

    // output projection
    gemm16<<<dim3(D_ / 128, M / 128), 256>>>(
        (const uint32_t*)attn, (const uint32_t*)wot, out, D_, NHH);
}

// round 15
// speedup vs baseline: 1.1463x; 1.0742x over previous
#include <cuda_runtime.h>
#include <cuda_fp16.h>
#include <math.h>
#include <stdint.h>

#define B_  2
#define T_  2048
#define D_  2048
#define NH_ 16
#define KH_ 4
#define H_  128

__device__ __half g_xqh [B_*T_*D_];
__device__ __half g_xkvh[B_*T_*D_];
__device__ __half g_wqt [NH_*H_*D_];
__device__ __half g_wkt [KH_*H_*D_];
__device__ __half g_wvt [KH_*H_*D_];
__device__ __half g_wot [D_*NH_*H_];
__device__ float2 g_scq [B_*T_*64];
__device__ float2 g_sck [B_*T_*64];
__device__ __half g_qh [B_*T_*NH_*H_];
__device__ __half g_kh [B_*T_*KH_*H_];
__device__ __half g_vt [B_*KH_*H_*T_];
__device__ __half g_attn[B_*T_*NH_*H_];

__device__ __forceinline__ uint32_t f2h2(float lo, float hi) {
    __half2 h = __floats2half2_rn(lo, hi);
    return *(uint32_t*)&h;
}

__device__ __forceinline__ float ex2f(float x) {
    float r;
    asm("ex2.approx.f32 %0, %1;" : "=f"(r) : "f"(x));
    return r;
}

__device__ __forceinline__ void cpasync16(void* dst, const void* src) {
    uint32_t d = (uint32_t)__cvta_generic_to_shared(dst);
    asm volatile("cp.async.cg.shared.global [%0], [%1], 16;\n" :: "r"(d), "l"(src));
}

__device__ __forceinline__ uint32_t smem_u32(const void* p) {
    return (uint32_t)__cvta_generic_to_shared(p);
}

__device__ __forceinline__ void mma16(float* c, const uint32_t* a, const uint32_t* b) {
    asm volatile(
        "mma.sync.aligned.m16n8k16.row.col.f32.f16.f16.f32 "
        "{%0,%1,%2,%3}, {%4,%5,%6,%7}, {%8,%9}, {%0,%1,%2,%3};\n"
        : "+f"(c[0]), "+f"(c[1]), "+f"(c[2]), "+f"(c[3])
        : "r"(a[0]), "r"(a[1]), "r"(a[2]), "r"(a[3]),
          "r"(b[0]), "r"(b[1]));
}

__device__ __forceinline__ void ldsm4(uint32_t& r0, uint32_t& r1,
                                      uint32_t& r2, uint32_t& r3, uint32_t addr) {
    asm volatile("ldmatrix.sync.aligned.m8n8.x4.shared.b16 {%0,%1,%2,%3}, [%4];"
                 : "=r"(r0), "=r"(r1), "=r"(r2), "=r"(r3) : "r"(addr));
}

// ---------------------------------------------------------------------------
// PREP (R14, unchanged): cvt inputs, transpose weights, rope tables
// ---------------------------------------------------------------------------
#define NCVT  ((B_*T_*D_) / 1024)
#define TQ_   ((NH_*H_/32) * (D_/32))
#define TK_   ((KH_*H_/32) * (D_/32))
#define TO_   ((D_/32) * (NH_*H_/32))
#define NROPE ((B_*T_) / 4)
#define PREP_GRID (2*NCVT + TQ_ + 2*TK_ + TO_ + NROPE)

__device__ __forceinline__
void tr_tile(const float* __restrict__ src, __half* __restrict__ dst,
             int R, int C, int c0, int r0, float (*tile)[33]) {
    int tx = threadIdx.x & 31, ty = threadIdx.x >> 5;
#pragma unroll
    for (int i = 0; i < 32; i += 8)
        tile[ty + i][tx] = src[(size_t)(r0 + ty + i) * C + c0 + tx];
    __syncthreads();
#pragma unroll
    for (int i = 0; i < 32; i += 8)
        dst[(size_t)(c0 + ty + i) * R + r0 + tx] = __float2half_rn(tile[tx][ty + i]);
}

__global__ void prep(const float* __restrict__ Xq, const float* __restrict__ Xkv,
                     __half2* __restrict__ xqh, __half2* __restrict__ xkvh,
                     const float* __restrict__ Wq, const float* __restrict__ Wk,
                     const float* __restrict__ Wv, const float* __restrict__ Wo,
                     __half* __restrict__ wqt, __half* __restrict__ wkt,
                     __half* __restrict__ wvt, __half* __restrict__ wot,
                     const int* __restrict__ qpos, const int* __restrict__ kpos,
                     float2* __restrict__ scq, float2* __restrict__ sck) {
    __shared__ float tile[32][33];
    int bid = blockIdx.x, tid = threadIdx.x;

    if (bid < 2 * NCVT) {
        const float* s = (bid < NCVT) ? Xq : Xkv;
        __half2* d = (bid < NCVT) ? xqh : xkvh;
        int i = (bid % NCVT) * 256 + tid;
        float4 a = ((const float4*)s)[i];
        d[2*i]   = __floats2half2_rn(a.x, a.y);
        d[2*i+1] = __floats2half2_rn(a.z, a.w);
        return;
    }
    bid -= 2 * NCVT;
    if (bid < TQ_) {
        int nx = NH_ * H_ / 32;
        tr_tile(Wq, wqt, D_, NH_*H_, (bid % nx) * 32, (bid / nx) * 32, tile);
        return;
    }
    bid -= TQ_;
    if (bid < 2 * TK_) {
        const float* s = (bid < TK_) ? Wk : Wv;
        __half* d = (bid < TK_) ? wkt : wvt;
        int r = bid % TK_, nx = KH_ * H_ / 32;
        tr_tile(s, d, D_, KH_*H_, (r % nx) * 32, (r / nx) * 32, tile);
        return;
    }
    bid -= 2 * TK_;
    if (bid < TO_) {
        int nx = D_ / 32;
        tr_tile(Wo, wot, NH_*H_, D_, (bid % nx) * 32, (bid / nx) * 32, tile);
        return;
    }
    bid -= TO_;
    {
        int token = bid * 4 + (tid >> 6);
        int i = tid & 63;
        double ts = exp(((double)i / 64.0) * 9.210340371976182736);
        double s_, c_;
        float angq = (float)qpos[token] / (float)ts;
        sincos((double)angq, &s_, &c_);
        scq[token * 64 + i] = make_float2((float)s_, (float)c_);
        float angk = (float)kpos[token] / (float)ts;
        sincos((double)angk, &s_, &c_);
        sck[token * 64 + i] = make_float2((float)s_, (float)c_);
    }
}

// ---------------------------------------------------------------------------
// Shared fp16 GEMM mainloop — fragment loads via ldmatrix.x4
// ---------------------------------------------------------------------------
#define GST 20
#define CST 133

__device__ __forceinline__
void gemm_mainloop(const uint32_t* __restrict__ A, const uint32_t* __restrict__ Bt,
                   int Kd, uint32_t* pool, float acc[4][4][4],
                   int brow, int bcol) {
    uint32_t* As = pool;
    uint32_t* Bs = pool + 5120;
    int tid  = threadIdx.x;
    int warp = tid >> 5, lane = tid & 31;
    int mw = (warp >> 2) * 64, nw = (warp & 3) * 32;
    int KW = Kd >> 1;

    // ldmatrix lane mappings
    int l16 = lane & 15, lh = lane >> 4;                 // A: rows, chunk
    int rowsel = ((lane >> 4) & 1) * 8 + (lane & 7);     // B: row within 16
    int offw   = ((lane >> 3) & 1) * 4;                  // B: chunk

#pragma unroll
    for (int mi = 0; mi < 4; mi++)
#pragma unroll
        for (int ni = 0; ni < 4; ni++)
#pragma unroll
            for (int j = 0; j < 4; j++) acc[mi][ni][j] = 0.f;

    const int nkt = Kd >> 5;

    auto load_stage = [&](int kt, int buf) {
        int kw0 = kt * 16;
#pragma unroll
        for (int u = 0; u < 2; u++) {
            int c = tid + 256 * u;
            int row = c >> 2, w4 = (c & 3) * 4;
            cpasync16(&As[buf * 2560 + row * GST + w4],
                      &A[(size_t)(brow + row) * KW + kw0 + w4]);
            cpasync16(&Bs[buf * 2560 + row * GST + w4],
                      &Bt[(size_t)(bcol + row) * KW + kw0 + w4]);
        }
    };

    uint32_t as_base = smem_u32(As);
    uint32_t bs_base = smem_u32(Bs);

    load_stage(0, 0);
    asm volatile("cp.async.commit_group;\n");

    for (int kt = 0; kt < nkt; kt++) {
        int buf = kt & 1;
        if (kt + 1 < nkt) {
            load_stage(kt + 1, buf ^ 1);
            asm volatile("cp.async.commit_group;\n");
            asm volatile("cp.async.wait_group 1;\n");
        } else {
            asm volatile("cp.async.wait_group 0;\n");
        }
        __syncthreads();

        uint32_t ab = as_base + (uint32_t)(buf * 2560 + (mw + l16) * GST + lh * 4) * 4;
        uint32_t bb = bs_base + (uint32_t)(buf * 2560 + (nw + rowsel) * GST + offw) * 4;

#pragma unroll
        for (int ks = 0; ks < 2; ks++) {
            uint32_t af[4][4], bf2[2][4];
#pragma unroll
            for (int mi = 0; mi < 4; mi++)
                ldsm4(af[mi][0], af[mi][1], af[mi][2], af[mi][3],
                      ab + (uint32_t)(mi * 16 * GST + ks * 8) * 4);
#pragma unroll
            for (int p = 0; p < 2; p++)
                ldsm4(bf2[p][0], bf2[p][1], bf2[p][2], bf2[p][3],
                      bb + (uint32_t)(p * 16 * GST + ks * 8) * 4);
#pragma unroll
            for (int mi = 0; mi < 4; mi++) {
#pragma unroll
                for (int ni = 0; ni < 4; ni++) {
                    const uint32_t* bfp = &bf2[ni >> 1][(ni & 1) * 2];
                    mma16(acc[mi][ni], af[mi], bfp);
                }
            }
        }
        __syncthreads();
    }
}

__device__ __forceinline__
void stage_pass(float* Cs, float acc[4][4][4], int p) {
    int tid = threadIdx.x, warp = tid >> 5, lane = tid & 31;
    int nw = (warp & 3) * 32;
    int lr = lane >> 2, lc = lane & 3;
    if ((warp >> 2) == p) {
#pragma unroll
        for (int mi = 0; mi < 4; mi++) {
#pragma unroll
            for (int ni = 0; ni < 4; ni++) {
                int r0 = mi * 16 + lr, cc = nw + ni * 8 + 2 * lc;
                Cs[r0 * CST + cc]           = acc[mi][ni][0];
                Cs[r0 * CST + cc + 1]       = acc[mi][ni][1];
                Cs[(r0 + 8) * CST + cc]     = acc[mi][ni][2];
                Cs[(r0 + 8) * CST + cc + 1] = acc[mi][ni][3];
            }
        }
    }
}

// ---------------------------------------------------------------------------
// PROJ_ALL (R14 structure, new mainloop)
// ---------------------------------------------------------------------------
__global__ __launch_bounds__(256, 2)
void proj_all(const uint32_t* __restrict__ xqh, const uint32_t* __restrict__ xkvh,
              const uint32_t* __restrict__ wqt, const uint32_t* __restrict__ wkt,
              const uint32_t* __restrict__ wvt,
              __half* __restrict__ qdst, __half* __restrict__ kdst,
              __half* __restrict__ vdst,
              const float2* __restrict__ scq, const float2* __restrict__ sck,
              float scale) {
    __shared__ uint32_t pool[10240];
    float acc[4][4][4];
    int bid = blockIdx.x, tid = threadIdx.x;
    float* Cs = (float*)pool;

    if (bid < 512) {
        int n = bid & 15, brow = (bid >> 4) * 128;
        gemm_mainloop(xqh, wqt, D_, pool, acc, brow, n * 128);
#pragma unroll
        for (int p = 0; p < 2; p++) {
            stage_pass(Cs, acc, p);
            __syncthreads();
            int row = tid >> 2, g = tid & 3;
            int token = brow + p * 64 + row;
            const float2* scrow = scq + (size_t)token * 64;
            __half* drow = qdst + (((size_t)token * NH_ + n) << 7);
#pragma unroll
            for (int j = 0; j < 16; j++) {
                int i = g * 16 + j;
                float2 scv = scrow[i];
                float x1 = Cs[row * CST + i];
                float x2 = Cs[row * CST + i + 64];
                drow[i]      = __float2half_rn((x1 * scv.y - x2 * scv.x) * scale);
                drow[i + 64] = __float2half_rn((x2 * scv.y + x1 * scv.x) * scale);
            }
            __syncthreads();
        }
    } else if (bid < 640) {
        int r = bid - 512;
        int kh = r & 3, brow = (r >> 2) * 128;
        gemm_mainloop(xkvh, wkt, D_, pool, acc, brow, kh * 128);
#pragma unroll
        for (int p = 0; p < 2; p++) {
            stage_pass(Cs, acc, p);
            __syncthreads();
            int row = tid >> 2, g = tid & 3;
            int token = brow + p * 64 + row;
            const float2* scrow = sck + (size_t)token * 64;
            __half* drow = kdst + (((size_t)token * KH_ + kh) << 7);
#pragma unroll
            for (int j = 0; j < 16; j++) {
                int i = g * 16 + j;
                float2 scv = scrow[i];
                float x1 = Cs[row * CST + i];
                float x2 = Cs[row * CST + i + 64];
                drow[i]      = __float2half_rn(x1 * scv.y - x2 * scv.x);
                drow[i + 64] = __float2half_rn(x2 * scv.y + x1 * scv.x);
            }
            __syncthreads();
        }
    } else {
        int r = bid - 640;
        int kh = r & 3, brow = (r >> 2) * 128;
        gemm_mainloop(xkvh, wvt, D_, pool, acc, brow, kh * 128);
#pragma unroll
        for (int p = 0; p < 2; p++) {
            stage_pass(Cs, acc, p);
            __syncthreads();
            int h = tid >> 1, half = tid & 1;
            int tglob = brow + p * 64 + half * 32;
            int b = tglob / T_, tloc = tglob % T_;
            __half* dstp = vdst + ((size_t)(b * KH_ + kh) * H_ + h) * T_ + tloc;
#pragma unroll
            for (int j = 0; j < 32; j++)
                dstp[j] = __float2half_rn(Cs[(half * 32 + j) * CST + h]);
            __syncthreads();
        }
    }
}

// ---------------------------------------------------------------------------
// Plain GEMM (output projection)
// ---------------------------------------------------------------------------
__global__ __launch_bounds__(256, 2)
void gemm16(const uint32_t* __restrict__ A, const uint32_t* __restrict__ Bt,
            float* __restrict__ C, int Nc, int Kd) {
    __shared__ uint32_t pool[10240];
    float acc[4][4][4];
    int brow = blockIdx.y * 128, bcol = blockIdx.x * 128;
    gemm_mainloop(A, Bt, Kd, pool, acc, brow, bcol);

    int tid = threadIdx.x, warp = tid >> 5, lane = tid & 31;
    int mw = (warp >> 2) * 64, nw = (warp & 3) * 32;
    int lr = lane >> 2, lc = lane & 3;
#pragma unroll
    for (int mi = 0; mi < 4; mi++) {
#pragma unroll
        for (int ni = 0; ni < 4; ni++) {
            int r0 = brow + mw + mi * 16 + lr;
            int cc = bcol + nw + ni * 8 + lc * 2;
            *(float2*)&C[(size_t)r0 * Nc + cc] =
                make_float2(acc[mi][ni][0], acc[mi][ni][1]);
            *(float2*)&C[(size_t)(r0 + 8) * Nc + cc] =
                make_float2(acc[mi][ni][2], acc[mi][ni][3]);
        }
    }
}

// ---------------------------------------------------------------------------
// FP16 flash attention (R13 core; K/V/P fragment loads via ldmatrix.x4)
// ---------------------------------------------------------------------------
#define KST  68
#define VSTW 68
#define PSTW 68
#define FA_SMEM ((2*128*KST + 2*128*VSTW + 8*16*PSTW) * 4)

__global__ __launch_bounds__(256, 1)
void flash16(const uint32_t* __restrict__ qh, const uint32_t* __restrict__ kk,
             const uint32_t* __restrict__ vt, uint32_t* __restrict__ o) {
    extern __shared__ uint32_t sm_u[];
    uint32_t* Ks = sm_u;
    uint32_t* Vs = Ks + 2 * 128 * KST;
    uint32_t* Ps = Vs + 2 * 128 * VSTW;

    int qt = (int)gridDim.x - 1 - (int)blockIdx.x;
    int n  = blockIdx.y;
    int b  = blockIdx.z;
    int khd = n >> 2;
    int tid = threadIdx.x, warp = tid >> 5, lane = tid & 31;
    int lr = lane >> 2, lc = lane & 3;
    int q0 = qt * 128;

    int l16 = lane & 15, lh = lane >> 4;
    int rowsel = ((lane >> 4) & 1) * 8 + (lane & 7);
    int offw   = ((lane >> 3) & 1) * 4;

    uint32_t qf[8][4];
#pragma unroll
    for (int pass = 0; pass < 2; pass++) {
#pragma unroll
        for (int u = 0; u < 4; u++) {
            int f = tid + 256 * u;
            int r = f >> 4, w4 = (f & 15) * 4;
            *(uint4*)(Ks + r * KST + w4) = *(const uint4*)(qh +
                ((size_t)((b * T_ + q0 + pass * 64 + r) * NH_ + n) << 6) + w4);
        }
        __syncthreads();
        if ((warp >> 2) == pass) {
            int mr = (warp & 3) * 16;
            uint32_t qbase = smem_u32(Ks) + (uint32_t)((mr + l16) * KST + lh * 4) * 4;
#pragma unroll
            for (int hs = 0; hs < 8; hs++)
                ldsm4(qf[hs][0], qf[hs][1], qf[hs][2], qf[hs][3],
                      qbase + (uint32_t)(hs * 8) * 4);
        }
        __syncthreads();
    }

    float m_[2] = {-1e30f, -1e30f};
    float l_[2] = {0.f, 0.f};
    float oacc[16][4];
#pragma unroll
    for (int ns = 0; ns < 16; ns++)
#pragma unroll
        for (int j = 0; j < 4; j++) oacc[ns][j] = 0.f;

    int row0 = q0 + warp * 16 + lr;
    int njt = qt + 1;

    auto load_kv = [&](int jt, int bufsel) {
        int s0 = jt * 128;
        uint32_t* Kd = Ks + bufsel * 128 * KST;
        uint32_t* Vd = Vs + bufsel * 128 * VSTW;
#pragma unroll
        for (int u = 0; u < 8; u++) {
            int f = tid + 256 * u;
            int r = f >> 4, w4 = (f & 15) * 4;
            cpasync16(Kd + r * KST + w4,
                      kk + ((size_t)((b * T_ + s0 + r) * KH_ + khd) << 6) + w4);
            cpasync16(Vd + r * VSTW + w4,
                      vt + ((((size_t)(b * KH_ + khd) * H_ + r) * T_ + s0) >> 1) + w4);
        }
    };

    load_kv(0, 0);
    asm volatile("cp.async.commit_group;\n");

    for (int jt = 0; jt < njt; jt++) {
        int buf = jt & 1;
        if (jt + 1 < njt) {
            load_kv(jt + 1, buf ^ 1);
            asm volatile("cp.async.commit_group;\n");
            asm volatile("cp.async.wait_group 1;\n");
        } else {
            asm volatile("cp.async.wait_group 0;\n");
        }
        __syncthreads();

        uint32_t kb0 = smem_u32(Ks) + (uint32_t)(buf * 128 * KST) * 4
                     + (uint32_t)(rowsel * KST + offw) * 4;
        uint32_t vb0 = smem_u32(Vs) + (uint32_t)(buf * 128 * VSTW) * 4
                     + (uint32_t)(rowsel * VSTW + offw) * 4;
        int s0 = jt * 128;

        // ---- S = Q K^T (K frags via ldmatrix.x4, 2 n-frags per load) ----
        float s_[16][4];
#pragma unroll
        for (int ns = 0; ns < 16; ns++)
#pragma unroll
            for (int j = 0; j < 4; j++) s_[ns][j] = 0.f;
#pragma unroll
        for (int hs = 0; hs < 8; hs++) {
#pragma unroll
            for (int np = 0; np < 8; np++) {
                uint32_t b0, b1, b2, b3;
                ldsm4(b0, b1, b2, b3,
                      kb0 + (uint32_t)(np * 16 * KST + hs * 8) * 4);
                uint32_t bfa[2] = {b0, b1}, bfb[2] = {b2, b3};
                mma16(s_[2 * np],     qf[hs], bfa);
                mma16(s_[2 * np + 1], qf[hs], bfb);
            }
        }

        if (jt == qt) {
#pragma unroll
            for (int ns = 0; ns < 16; ns++) {
                int col = s0 + ns * 8 + 2 * lc;
                if (col > row0)     s_[ns][0] = -1e30f;
                if (col + 1 > row0) s_[ns][1] = -1e30f;
                if (col > row0 + 8)     s_[ns][2] = -1e30f;
                if (col + 1 > row0 + 8) s_[ns][3] = -1e30f;
            }
        }

        float mx0 = -1e30f, mx1 = -1e30f;
#pragma unroll
        for (int ns = 0; ns < 16; ns++) {
            mx0 = fmaxf(mx0, fmaxf(s_[ns][0], s_[ns][1]));
            mx1 = fmaxf(mx1, fmaxf(s_[ns][2], s_[ns][3]));
        }
        mx0 = fmaxf(mx0, __shfl_xor_sync(0xffffffffu, mx0, 1));
        mx0 = fmaxf(mx0, __shfl_xor_sync(0xffffffffu, mx0, 2));
        mx1 = fmaxf(mx1, __shfl_xor_sync(0xffffffffu, mx1, 1));
        mx1 = fmaxf(mx1, __shfl_xor_sync(0xffffffffu, mx1, 2));
        float mn0 = fmaxf(m_[0], mx0), mn1 = fmaxf(m_[1], mx1);
        float a0 = ex2f(m_[0] - mn0), a1 = ex2f(m_[1] - mn1);
        float sum0 = 0.f, sum1 = 0.f;
        uint32_t* Pw = Ps + warp * 16 * PSTW;
#pragma unroll
        for (int ns = 0; ns < 16; ns++) {
            float p0 = ex2f(s_[ns][0] - mn0);
            float p1 = ex2f(s_[ns][1] - mn0);
            float p2 = ex2f(s_[ns][2] - mn1);
            float p3 = ex2f(s_[ns][3] - mn1);
            sum0 += p0 + p1;
            sum1 += p2 + p3;
            Pw[lr * PSTW + ns * 4 + lc]       = f2h2(p0, p1);
            Pw[(lr + 8) * PSTW + ns * 4 + lc] = f2h2(p2, p3);
        }
        sum0 += __shfl_xor_sync(0xffffffffu, sum0, 1);
        sum0 += __shfl_xor_sync(0xffffffffu, sum0, 2);
        sum1 += __shfl_xor_sync(0xffffffffu, sum1, 1);
        sum1 += __shfl_xor_sync(0xffffffffu, sum1, 2);
        l_[0] = l_[0] * a0 + sum0;
        l_[1] = l_[1] * a1 + sum1;
        m_[0] = mn0; m_[1] = mn1;

#pragma unroll
        for (int ns = 0; ns < 16; ns++) {
            oacc[ns][0] *= a0; oacc[ns][1] *= a0;
            oacc[ns][2] *= a1; oacc[ns][3] *= a1;
        }
        __syncwarp();

        // ---- O += P V (P A-frags + V B-frags via ldmatrix.x4) ----
        uint32_t pb0 = smem_u32(Pw) + (uint32_t)(l16 * PSTW + lh * 4) * 4;
#pragma unroll
        for (int ks = 0; ks < 8; ks++) {
            uint32_t af[4];
            ldsm4(af[0], af[1], af[2], af[3], pb0 + (uint32_t)(ks * 8) * 4);
#pragma unroll
            for (int np = 0; np < 8; np++) {
                uint32_t v0, v1, v2, v3;
                ldsm4(v0, v1, v2, v3,
                      vb0 + (uint32_t)(np * 16 * VSTW + ks * 8) * 4);
                uint32_t bfa[2] = {v0, v1}, bfb[2] = {v2, v3};
                mma16(oacc[2 * np],     af, bfa);
                mma16(oacc[2 * np + 1], af, bfb);
            }
        }
        __syncthreads();
    }

    float inv0 = 1.f / l_[0], inv1 = 1.f / l_[1];
    size_t wb0 = ((size_t)((b * T_ + row0) * NH_ + n) << 6);
    size_t wb1 = ((size_t)((b * T_ + row0 + 8) * NH_ + n) << 6);
#pragma unroll
    for (int ns = 0; ns < 16; ns++) {
        o[wb0 + ns * 4 + lc] = f2h2(oacc[ns][0] * inv0, oacc[ns][1] * inv0);
        o[wb1 + ns * 4 + lc] = f2h2(oacc[ns][2] * inv1, oacc[ns][3] * inv1);
    }
}

// ---------------------------------------------------------------------------
extern "C" void kernel_launch(void* const* d_in, const int* in_sizes, int n_in,
                              void* d_out, int out_size) {
    const float* Xq   = (const float*)d_in[0];
    const float* Xkv  = (const float*)d_in[1];
    const int*   qpos = (const int*)  d_in[2];
    const int*   kpos = (const int*)  d_in[3];
    const float* Wq   = (const float*)d_in[4];
    const float* Wk   = (const float*)d_in[5];
    const float* Wv   = (const float*)d_in[6];
    const float* Wo   = (const float*)d_in[7];
    float* out = (float*)d_out;

    __half *xqh, *xkvh, *wqt, *wkt, *wvt, *wot, *qh, *kh, *vt, *attn;
    float2 *scq, *sck;
    cudaGetSymbolAddress((void**)&xqh,  g_xqh);
    cudaGetSymbolAddress((void**)&xkvh, g_xkvh);
    cudaGetSymbolAddress((void**)&wqt,  g_wqt);
    cudaGetSymbolAddress((void**)&wkt,  g_wkt);
    cudaGetSymbolAddress((void**)&wvt,  g_wvt);
    cudaGetSymbolAddress((void**)&wot,  g_wot);
    cudaGetSymbolAddress((void**)&scq,  g_scq);
    cudaGetSymbolAddress((void**)&sck,  g_sck);
    cudaGetSymbolAddress((void**)&qh,   g_qh);
    cudaGetSymbolAddress((void**)&kh,   g_kh);
    cudaGetSymbolAddress((void**)&vt,   g_vt);
    cudaGetSymbolAddress((void**)&attn, g_attn);

    const int M = B_ * T_;  // 4096
    const int NHH = NH_ * H_;
    const float scale = 0.08838834764831845f * 1.4426950408889634f;

    prep<<<PREP_GRID, 256>>>(Xq, Xkv, (__half2*)xqh, (__half2*)xkvh,
                             Wq, Wk, Wv, Wo, wqt, wkt, wvt, wot,
                             qpos, kpos, scq, sck);

    proj_all<<<768, 256>>>(
        (const uint32_t*)xqh, (const uint32_t*)xkvh,
        (const uint32_t*)wqt, (const uint32_t*)wkt, (const uint32_t*)wvt,
        qh, kh, vt, scq, sck, scale);

    cudaFuncSetAttribute(flash16,
                         cudaFuncAttributeMaxDynamicSharedMemorySize, FA_SMEM);
    flash16<<<dim3(T_ / 128, NH_, B_), 256, FA_SMEM>>>(
        (const uint32_t*)qh, (const uint32_t*)kh, (const uint32_t*)vt,
        (uint32_t*)attn);

    gemm16<<<dim3(D_ / 128, M / 128), 256>>>(
        (const uint32_t*)attn, (const uint32_t*)wot, out, D_, NHH);
}

// round 16
// speedup vs baseline: 1.1778x; 1.0274x over previous
#include <cuda_runtime.h>
#include <cuda_fp16.h>
#include <math.h>
#include <stdint.h>

#define B_  2
#define T_  2048
#define D_  2048
#define NH_ 16
#define KH_ 4
#define H_  128

__device__ __half g_xqh [B_*T_*D_];
__device__ __half g_xkvh[B_*T_*D_];
__device__ __half g_wqt [NH_*H_*D_];
__device__ __half g_wkt [KH_*H_*D_];
__device__ __half g_wvt [KH_*H_*D_];
__device__ __half g_wot [D_*NH_*H_];
__device__ float2 g_scq [B_*T_*64];
__device__ float2 g_sck [B_*T_*64];
__device__ __half g_qh [B_*T_*NH_*H_];
__device__ __half g_kh [B_*T_*KH_*H_];
__device__ __half g_vt [B_*KH_*H_*T_];
__device__ __half g_attn[B_*T_*NH_*H_];

__device__ __forceinline__ uint32_t f2h2(float lo, float hi) {
    __half2 h = __floats2half2_rn(lo, hi);
    return *(uint32_t*)&h;
}

__device__ __forceinline__ float ex2f(float x) {
    float r;
    asm("ex2.approx.f32 %0, %1;" : "=f"(r) : "f"(x));
    return r;
}

__device__ __forceinline__ void cpasync16(void* dst, const void* src) {
    uint32_t d = (uint32_t)__cvta_generic_to_shared(dst);
    asm volatile("cp.async.cg.shared.global [%0], [%1], 16;\n" :: "r"(d), "l"(src));
}

__device__ __forceinline__ uint32_t smem_u32(const void* p) {
    return (uint32_t)__cvta_generic_to_shared(p);
}

__device__ __forceinline__ void mma16(float* c, const uint32_t* a, const uint32_t* b) {
    asm volatile(
        "mma.sync.aligned.m16n8k16.row.col.f32.f16.f16.f32 "
        "{%0,%1,%2,%3}, {%4,%5,%6,%7}, {%8,%9}, {%0,%1,%2,%3};\n"
        : "+f"(c[0]), "+f"(c[1]), "+f"(c[2]), "+f"(c[3])
        : "r"(a[0]), "r"(a[1]), "r"(a[2]), "r"(a[3]),
          "r"(b[0]), "r"(b[1]));
}

__device__ __forceinline__ void ldsm4(uint32_t& r0, uint32_t& r1,
                                      uint32_t& r2, uint32_t& r3, uint32_t addr) {
    asm volatile("ldmatrix.sync.aligned.m8n8.x4.shared.b16 {%0,%1,%2,%3}, [%4];"
                 : "=r"(r0), "=r"(r1), "=r"(r2), "=r"(r3) : "r"(addr));
}

// ---------------------------------------------------------------------------
// PREP (unchanged): cvt inputs, transpose weights, rope tables
// ---------------------------------------------------------------------------
#define NCVT  ((B_*T_*D_) / 1024)
#define TQ_   ((NH_*H_/32) * (D_/32))
#define TK_   ((KH_*H_/32) * (D_/32))
#define TO_   ((D_/32) * (NH_*H_/32))
#define NROPE ((B_*T_) / 4)
#define PREP_GRID (2*NCVT + TQ_ + 2*TK_ + TO_ + NROPE)

__device__ __forceinline__
void tr_tile(const float* __restrict__ src, __half* __restrict__ dst,
             int R, int C, int c0, int r0, float (*tile)[33]) {
    int tx = threadIdx.x & 31, ty = threadIdx.x >> 5;
#pragma unroll
    for (int i = 0; i < 32; i += 8)
        tile[ty + i][tx] = src[(size_t)(r0 + ty + i) * C + c0 + tx];
    __syncthreads();
#pragma unroll
    for (int i = 0; i < 32; i += 8)
        dst[(size_t)(c0 + ty + i) * R + r0 + tx] = __float2half_rn(tile[tx][ty + i]);
}

__global__ void prep(const float* __restrict__ Xq, const float* __restrict__ Xkv,
                     __half2* __restrict__ xqh, __half2* __restrict__ xkvh,
                     const float* __restrict__ Wq, const float* __restrict__ Wk,
                     const float* __restrict__ Wv, const float* __restrict__ Wo,
                     __half* __restrict__ wqt, __half* __restrict__ wkt,
                     __half* __restrict__ wvt, __half* __restrict__ wot,
                     const int* __restrict__ qpos, const int* __restrict__ kpos,
                     float2* __restrict__ scq, float2* __restrict__ sck) {
    __shared__ float tile[32][33];
    int bid = blockIdx.x, tid = threadIdx.x;

    if (bid < 2 * NCVT) {
        const float* s = (bid < NCVT) ? Xq : Xkv;
        __half2* d = (bid < NCVT) ? xqh : xkvh;
        int i = (bid % NCVT) * 256 + tid;
        float4 a = ((const float4*)s)[i];
        d[2*i]   = __floats2half2_rn(a.x, a.y);
        d[2*i+1] = __floats2half2_rn(a.z, a.w);
        return;
    }
    bid -= 2 * NCVT;
    if (bid < TQ_) {
        int nx = NH_ * H_ / 32;
        tr_tile(Wq, wqt, D_, NH_*H_, (bid % nx) * 32, (bid / nx) * 32, tile);
        return;
    }
    bid -= TQ_;
    if (bid < 2 * TK_) {
        const float* s = (bid < TK_) ? Wk : Wv;
        __half* d = (bid < TK_) ? wkt : wvt;
        int r = bid % TK_, nx = KH_ * H_ / 32;
        tr_tile(s, d, D_, KH_*H_, (r % nx) * 32, (r / nx) * 32, tile);
        return;
    }
    bid -= 2 * TK_;
    if (bid < TO_) {
        int nx = D_ / 32;
        tr_tile(Wo, wot, NH_*H_, D_, (bid % nx) * 32, (bid / nx) * 32, tile);
        return;
    }
    bid -= TO_;
    {
        int token = bid * 4 + (tid >> 6);
        int i = tid & 63;
        double ts = exp(((double)i / 64.0) * 9.210340371976182736);
        double s_, c_;
        float angq = (float)qpos[token] / (float)ts;
        sincos((double)angq, &s_, &c_);
        scq[token * 64 + i] = make_float2((float)s_, (float)c_);
        float angk = (float)kpos[token] / (float)ts;
        sincos((double)angk, &s_, &c_);
        sck[token * 64 + i] = make_float2((float)s_, (float)c_);
    }
}

// ---------------------------------------------------------------------------
// Shared fp16 GEMM mainloop — ldmatrix frags, SINGLE sync per k-tile
// ---------------------------------------------------------------------------
#define GST 20
#define CST 133

__device__ __forceinline__
void gemm_mainloop(const uint32_t* __restrict__ A, const uint32_t* __restrict__ Bt,
                   int Kd, uint32_t* pool, float acc[4][4][4],
                   int brow, int bcol) {
    uint32_t* As = pool;
    uint32_t* Bs = pool + 5120;
    int tid  = threadIdx.x;
    int warp = tid >> 5, lane = tid & 31;
    int mw = (warp >> 2) * 64, nw = (warp & 3) * 32;

    int l16 = lane & 15, lh = lane >> 4;
    int rowsel = ((lane >> 4) & 1) * 8 + (lane & 7);
    int offw   = ((lane >> 3) & 1) * 4;

#pragma unroll
    for (int mi = 0; mi < 4; mi++)
#pragma unroll
        for (int ni = 0; ni < 4; ni++)
#pragma unroll
            for (int j = 0; j < 4; j++) acc[mi][ni][j] = 0.f;

    const int nkt = Kd >> 5;
    int KW = Kd >> 1;

    auto load_stage = [&](int kt, int buf) {
        int kw0 = kt * 16;
#pragma unroll
        for (int u = 0; u < 2; u++) {
            int c = tid + 256 * u;
            int row = c >> 2, w4 = (c & 3) * 4;
            cpasync16(&As[buf * 2560 + row * GST + w4],
                      &A[(size_t)(brow + row) * KW + kw0 + w4]);
            cpasync16(&Bs[buf * 2560 + row * GST + w4],
                      &Bt[(size_t)(bcol + row) * KW + kw0 + w4]);
        }
        asm volatile("cp.async.commit_group;\n");
    };

    uint32_t as_base = smem_u32(As);
    uint32_t bs_base = smem_u32(Bs);

    load_stage(0, 0);

    for (int kt = 0; kt < nkt; kt++) {
        int buf = kt & 1;
        asm volatile("cp.async.wait_group 0;\n");
        __syncthreads();
        // issue next-stage load AFTER the barrier: overwrites buf(kt-1),
        // which every warp finished reading before arriving here.
        if (kt + 1 < nkt) load_stage(kt + 1, buf ^ 1);

        uint32_t ab = as_base + (uint32_t)(buf * 2560 + (mw + l16) * GST + lh * 4) * 4;
        uint32_t bb = bs_base + (uint32_t)(buf * 2560 + (nw + rowsel) * GST + offw) * 4;

#pragma unroll
        for (int ks = 0; ks < 2; ks++) {
            uint32_t af[4][4], bf2[2][4];
#pragma unroll
            for (int mi = 0; mi < 4; mi++)
                ldsm4(af[mi][0], af[mi][1], af[mi][2], af[mi][3],
                      ab + (uint32_t)(mi * 16 * GST + ks * 8) * 4);
#pragma unroll
            for (int p = 0; p < 2; p++)
                ldsm4(bf2[p][0], bf2[p][1], bf2[p][2], bf2[p][3],
                      bb + (uint32_t)(p * 16 * GST + ks * 8) * 4);
#pragma unroll
            for (int mi = 0; mi < 4; mi++) {
#pragma unroll
                for (int ni = 0; ni < 4; ni++) {
                    const uint32_t* bfp = &bf2[ni >> 1][(ni & 1) * 2];
                    mma16(acc[mi][ni], af[mi], bfp);
                }
            }
        }
    }
    __syncthreads();   // protect pool reuse by epilogue staging
}

__device__ __forceinline__
void stage_pass(float* Cs, float acc[4][4][4], int p) {
    int tid = threadIdx.x, warp = tid >> 5, lane = tid & 31;
    int nw = (warp & 3) * 32;
    int lr = lane >> 2, lc = lane & 3;
    if ((warp >> 2) == p) {
#pragma unroll
        for (int mi = 0; mi < 4; mi++) {
#pragma unroll
            for (int ni = 0; ni < 4; ni++) {
                int r0 = mi * 16 + lr, cc = nw + ni * 8 + 2 * lc;
                Cs[r0 * CST + cc]           = acc[mi][ni][0];
                Cs[r0 * CST + cc + 1]       = acc[mi][ni][1];
                Cs[(r0 + 8) * CST + cc]     = acc[mi][ni][2];
                Cs[(r0 + 8) * CST + cc + 1] = acc[mi][ni][3];
            }
        }
    }
}

// ---------------------------------------------------------------------------
// PROJ_ALL (unchanged structure, new mainloop)
// ---------------------------------------------------------------------------
__global__ __launch_bounds__(256, 2)
void proj_all(const uint32_t* __restrict__ xqh, const uint32_t* __restrict__ xkvh,
              const uint32_t* __restrict__ wqt, const uint32_t* __restrict__ wkt,
              const uint32_t* __restrict__ wvt,
              __half* __restrict__ qdst, __half* __restrict__ kdst,
              __half* __restrict__ vdst,
              const float2* __restrict__ scq, const float2* __restrict__ sck,
              float scale) {
    __shared__ uint32_t pool[10240];
    float acc[4][4][4];
    int bid = blockIdx.x, tid = threadIdx.x;
    float* Cs = (float*)pool;

    if (bid < 512) {
        int n = bid & 15, brow = (bid >> 4) * 128;
        gemm_mainloop(xqh, wqt, D_, pool, acc, brow, n * 128);
#pragma unroll
        for (int p = 0; p < 2; p++) {
            stage_pass(Cs, acc, p);
            __syncthreads();
            int row = tid >> 2, g = tid & 3;
            int token = brow + p * 64 + row;
            const float2* scrow = scq + (size_t)token * 64;
            __half* drow = qdst + (((size_t)token * NH_ + n) << 7);
#pragma unroll
            for (int j = 0; j < 16; j++) {
                int i = g * 16 + j;
                float2 scv = scrow[i];
                float x1 = Cs[row * CST + i];
                float x2 = Cs[row * CST + i + 64];
                drow[i]      = __float2half_rn((x1 * scv.y - x2 * scv.x) * scale);
                drow[i + 64] = __float2half_rn((x2 * scv.y + x1 * scv.x) * scale);
            }
            __syncthreads();
        }
    } else if (bid < 640) {
        int r = bid - 512;
        int kh = r & 3, brow = (r >> 2) * 128;
        gemm_mainloop(xkvh, wkt, D_, pool, acc, brow, kh * 128);
#pragma unroll
        for (int p = 0; p < 2; p++) {
            stage_pass(Cs, acc, p);
            __syncthreads();
            int row = tid >> 2, g = tid & 3;
            int token = brow + p * 64 + row;
            const float2* scrow = sck + (size_t)token * 64;
            __half* drow = kdst + (((size_t)token * KH_ + kh) << 7);
#pragma unroll
            for (int j = 0; j < 16; j++) {
                int i = g * 16 + j;
                float2 scv = scrow[i];
                float x1 = Cs[row * CST + i];
                float x2 = Cs[row * CST + i + 64];
                drow[i]      = __float2half_rn(x1 * scv.y - x2 * scv.x);
                drow[i + 64] = __float2half_rn(x2 * scv.y + x1 * scv.x);
            }
            __syncthreads();
        }
    } else {
        int r = bid - 640;
        int kh = r & 3, brow = (r >> 2) * 128;
        gemm_mainloop(xkvh, wvt, D_, pool, acc, brow, kh * 128);
#pragma unroll
        for (int p = 0; p < 2; p++) {
            stage_pass(Cs, acc, p);
            __syncthreads();
            int h = tid >> 1, half = tid & 1;
            int tglob = brow + p * 64 + half * 32;
            int b = tglob / T_, tloc = tglob % T_;
            __half* dstp = vdst + ((size_t)(b * KH_ + kh) * H_ + h) * T_ + tloc;
#pragma unroll
            for (int j = 0; j < 32; j++)
                dstp[j] = __float2half_rn(Cs[(half * 32 + j) * CST + h]);
            __syncthreads();
        }
    }
}

// ---------------------------------------------------------------------------
// Plain GEMM (output projection)
// ---------------------------------------------------------------------------
__global__ __launch_bounds__(256, 2)
void gemm16(const uint32_t* __restrict__ A, const uint32_t* __restrict__ Bt,
            float* __restrict__ C, int Nc, int Kd) {
    __shared__ uint32_t pool[10240];
    float acc[4][4][4];
    int brow = blockIdx.y * 128, bcol = blockIdx.x * 128;
    gemm_mainloop(A, Bt, Kd, pool, acc, brow, bcol);

    int tid = threadIdx.x, warp = tid >> 5, lane = tid & 31;
    int mw = (warp >> 2) * 64, nw = (warp & 3) * 32;
    int lr = lane >> 2, lc = lane & 3;
#pragma unroll
    for (int mi = 0; mi < 4; mi++) {
#pragma unroll
        for (int ni = 0; ni < 4; ni++) {
            int r0 = brow + mw + mi * 16 + lr;
            int cc = bcol + nw + ni * 8 + lc * 2;
            *(float2*)&C[(size_t)r0 * Nc + cc] =
                make_float2(acc[mi][ni][0], acc[mi][ni][1]);
            *(float2*)&C[(size_t)(r0 + 8) * Nc + cc] =
                make_float2(acc[mi][ni][2], acc[mi][ni][3]);
        }
    }
}

// ---------------------------------------------------------------------------
// FP16 flash attention — ldmatrix frags, SINGLE sync per kv-tile
// ---------------------------------------------------------------------------
#define KST  68
#define VSTW 68
#define PSTW 68
#define FA_SMEM ((2*128*KST + 2*128*VSTW + 8*16*PSTW) * 4)

__global__ __launch_bounds__(256, 1)
void flash16(const uint32_t* __restrict__ qh, const uint32_t* __restrict__ kk,
             const uint32_t* __restrict__ vt, uint32_t* __restrict__ o) {
    extern __shared__ uint32_t sm_u[];
    uint32_t* Ks = sm_u;
    uint32_t* Vs = Ks + 2 * 128 * KST;
    uint32_t* Ps = Vs + 2 * 128 * VSTW;

    int qt = (int)gridDim.x - 1 - (int)blockIdx.x;
    int n  = blockIdx.y;
    int b  = blockIdx.z;
    int khd = n >> 2;
    int tid = threadIdx.x, warp = tid >> 5, lane = tid & 31;
    int lr = lane >> 2, lc = lane & 3;
    int q0 = qt * 128;

    int l16 = lane & 15, lh = lane >> 4;
    int rowsel = ((lane >> 4) & 1) * 8 + (lane & 7);
    int offw   = ((lane >> 3) & 1) * 4;

    uint32_t qf[8][4];
#pragma unroll
    for (int pass = 0; pass < 2; pass++) {
#pragma unroll
        for (int u = 0; u < 4; u++) {
            int f = tid + 256 * u;
            int r = f >> 4, w4 = (f & 15) * 4;
            *(uint4*)(Ks + r * KST + w4) = *(const uint4*)(qh +
                ((size_t)((b * T_ + q0 + pass * 64 + r) * NH_ + n) << 6) + w4);
        }
        __syncthreads();
        if ((warp >> 2) == pass) {
            int mr = (warp & 3) * 16;
            uint32_t qbase = smem_u32(Ks) + (uint32_t)((mr + l16) * KST + lh * 4) * 4;
#pragma unroll
            for (int hs = 0; hs < 8; hs++)
                ldsm4(qf[hs][0], qf[hs][1], qf[hs][2], qf[hs][3],
                      qbase + (uint32_t)(hs * 8) * 4);
        }
        __syncthreads();
    }

    float m_[2] = {-1e30f, -1e30f};
    float l_[2] = {0.f, 0.f};
    float oacc[16][4];
#pragma unroll
    for (int ns = 0; ns < 16; ns++)
#pragma unroll
        for (int j = 0; j < 4; j++) oacc[ns][j] = 0.f;

    int row0 = q0 + warp * 16 + lr;
    int njt = qt + 1;

    auto load_kv = [&](int jt, int bufsel) {
        int s0 = jt * 128;
        uint32_t* Kd = Ks + bufsel * 128 * KST;
        uint32_t* Vd = Vs + bufsel * 128 * VSTW;
#pragma unroll
        for (int u = 0; u < 8; u++) {
            int f = tid + 256 * u;
            int r = f >> 4, w4 = (f & 15) * 4;
            cpasync16(Kd + r * KST + w4,
                      kk + ((size_t)((b * T_ + s0 + r) * KH_ + khd) << 6) + w4);
            cpasync16(Vd + r * VSTW + w4,
                      vt + ((((size_t)(b * KH_ + khd) * H_ + r) * T_ + s0) >> 1) + w4);
        }
        asm volatile("cp.async.commit_group;\n");
    };

    load_kv(0, 0);

    for (int jt = 0; jt < njt; jt++) {
        int buf = jt & 1;
        asm volatile("cp.async.wait_group 0;\n");
        __syncthreads();
        // issue next tile's loads after the barrier (overwrites buf jt-1,
        // fully consumed by every warp before this barrier)
        if (jt + 1 < njt) load_kv(jt + 1, buf ^ 1);

        uint32_t kb0 = smem_u32(Ks) + (uint32_t)(buf * 128 * KST) * 4
                     + (uint32_t)(rowsel * KST + offw) * 4;
        uint32_t vb0 = smem_u32(Vs) + (uint32_t)(buf * 128 * VSTW) * 4
                     + (uint32_t)(rowsel * VSTW + offw) * 4;
        int s0 = jt * 128;

        float s_[16][4];
#pragma unroll
        for (int ns = 0; ns < 16; ns++)
#pragma unroll
            for (int j = 0; j < 4; j++) s_[ns][j] = 0.f;
#pragma unroll
        for (int hs = 0; hs < 8; hs++) {
#pragma unroll
            for (int np = 0; np < 8; np++) {
                uint32_t b0, b1, b2, b3;
                ldsm4(b0, b1, b2, b3,
                      kb0 + (uint32_t)(np * 16 * KST + hs * 8) * 4);
                uint32_t bfa[2] = {b0, b1}, bfb[2] = {b2, b3};
                mma16(s_[2 * np],     qf[hs], bfa);
                mma16(s_[2 * np + 1], qf[hs], bfb);
            }
        }

        if (jt == qt) {
#pragma unroll
            for (int ns = 0; ns < 16; ns++) {
                int col = s0 + ns * 8 + 2 * lc;
                if (col > row0)     s_[ns][0] = -1e30f;
                if (col + 1 > row0) s_[ns][1] = -1e30f;
                if (col > row0 + 8)     s_[ns][2] = -1e30f;
                if (col + 1 > row0 + 8) s_[ns][3] = -1e30f;
            }
        }

        float mx0 = -1e30f, mx1 = -1e30f;
#pragma unroll
        for (int ns = 0; ns < 16; ns++) {
            mx0 = fmaxf(mx0, fmaxf(s_[ns][0], s_[ns][1]));
            mx1 = fmaxf(mx1, fmaxf(s_[ns][2], s_[ns][3]));
        }
        mx0 = fmaxf(mx0, __shfl_xor_sync(0xffffffffu, mx0, 1));
        mx0 = fmaxf(mx0, __shfl_xor_sync(0xffffffffu, mx0, 2));
        mx1 = fmaxf(mx1, __shfl_xor_sync(0xffffffffu, mx1, 1));
        mx1 = fmaxf(mx1, __shfl_xor_sync(0xffffffffu, mx1, 2));
        float mn0 = fmaxf(m_[0], mx0), mn1 = fmaxf(m_[1], mx1);
        float a0 = ex2f(m_[0] - mn0), a1 = ex2f(m_[1] - mn1);
        float sum0 = 0.f, sum1 = 0.f;
        uint32_t* Pw = Ps + warp * 16 * PSTW;
#pragma unroll
        for (int ns = 0; ns < 16; ns++) {
            float p0 = ex2f(s_[ns][0] - mn0);
            float p1 = ex2f(s_[ns][1] - mn0);
            float p2 = ex2f(s_[ns][2] - mn1);
            float p3 = ex2f(s_[ns][3] - mn1);
            sum0 += p0 + p1;
            sum1 += p2 + p3;
            Pw[lr * PSTW + ns * 4 + lc]       = f2h2(p0, p1);
            Pw[(lr + 8) * PSTW + ns * 4 + lc] = f2h2(p2, p3);
        }
        sum0 += __shfl_xor_sync(0xffffffffu, sum0, 1);
        sum0 += __shfl_xor_sync(0xffffffffu, sum0, 2);
        sum1 += __shfl_xor_sync(0xffffffffu, sum1, 1);
        sum1 += __shfl_xor_sync(0xffffffffu, sum1, 2);
        l_[0] = l_[0] * a0 + sum0;
        l_[1] = l_[1] * a1 + sum1;
        m_[0] = mn0; m_[1] = mn1;

#pragma unroll
        for (int ns = 0; ns < 16; ns++) {
            oacc[ns][0] *= a0; oacc[ns][1] *= a0;
            oacc[ns][2] *= a1; oacc[ns][3] *= a1;
        }
        __syncwarp();

        uint32_t pb0 = smem_u32(Pw) + (uint32_t)(l16 * PSTW + lh * 4) * 4;
#pragma unroll
        for (int ks = 0; ks < 8; ks++) {
            uint32_t af[4];
            ldsm4(af[0], af[1], af[2], af[3], pb0 + (uint32_t)(ks * 8) * 4);
#pragma unroll
            for (int np = 0; np < 8; np++) {
                uint32_t v0, v1, v2, v3;
                ldsm4(v0, v1, v2, v3,
                      vb0 + (uint32_t)(np * 16 * VSTW + ks * 8) * 4);
                uint32_t bfa[2] = {v0, v1}, bfb[2] = {v2, v3};
                mma16(oacc[2 * np],     af, bfa);
                mma16(oacc[2 * np + 1], af, bfb);
            }
        }
    }

    float inv0 = 1.f / l_[0], inv1 = 1.f / l_[1];
    size_t wb0 = ((size_t)((b * T_ + row0) * NH_ + n) << 6);
    size_t wb1 = ((size_t)((b * T_ + row0 + 8) * NH_ + n) << 6);
#pragma unroll
    for (int ns = 0; ns < 16; ns++) {
        o[wb0 + ns * 4 + lc] = f2h2(oacc[ns][0] * inv0, oacc[ns][1] * inv0);
        o[wb1 + ns * 4 + lc] = f2h2(oacc[ns][2] * inv1, oacc[ns][3] * inv1);
    }
}

// ---------------------------------------------------------------------------
extern "C" void kernel_launch(void* const* d_in, const int* in_sizes, int n_in,
                              void* d_out, int out_size) {
    const float* Xq   = (const float*)d_in[0];
    const float* Xkv  = (const float*)d_in[1];
    const int*   qpos = (const int*)  d_in[2];
    const int*   kpos = (const int*)  d_in[3];
    const float* Wq   = (const float*)d_in[4];
    const float* Wk   = (const float*)d_in[5];
    const float* Wv   = (const float*)d_in[6];
    const float* Wo   = (const float*)d_in[7];
    float* out = (float*)d_out;

    __half *xqh, *xkvh, *wqt, *wkt, *wvt, *wot, *qh, *kh, *vt, *attn;
    float2 *scq, *sck;
    cudaGetSymbolAddress((void**)&xqh,  g_xqh);
    cudaGetSymbolAddress((void**)&xkvh, g_xkvh);
    cudaGetSymbolAddress((void**)&wqt,  g_wqt);
    cudaGetSymbolAddress((void**)&wkt,  g_wkt);
    cudaGetSymbolAddress((void**)&wvt,  g_wvt);
    cudaGetSymbolAddress((void**)&wot,  g_wot);
    cudaGetSymbolAddress((void**)&scq,  g_scq);
    cudaGetSymbolAddress((void**)&sck,  g_sck);
    cudaGetSymbolAddress((void**)&qh,   g_qh);
    cudaGetSymbolAddress((void**)&kh,   g_kh);
    cudaGetSymbolAddress((void**)&vt,   g_vt);
    cudaGetSymbolAddress((void**)&attn, g_attn);

    const int M = B_ * T_;
    const int NHH = NH_ * H_;
    const float scale = 0.08838834764831845f * 1.4426950408889634f;

    prep<<<PREP_GRID, 256>>>(Xq, Xkv, (__half2*)xqh, (__half2*)xkvh,
                             Wq, Wk, Wv, Wo, wqt, wkt, wvt, wot,
                             qpos, kpos, scq, sck);

    proj_all<<<768, 256>>>(
        (const uint32_t*)xqh, (const uint32_t*)xkvh,
        (const uint32_t*)wqt, (const uint32_t*)wkt, (const uint32_t*)wvt,
        qh, kh, vt, scq, sck, scale);

    cudaFuncSetAttribute(flash16,
                         cudaFuncAttributeMaxDynamicSharedMemorySize, FA_SMEM);
    flash16<<<dim3(T_ / 128, NH_, B_), 256, FA_SMEM>>>(
        (const uint32_t*)qh, (const uint32_t*)kh, (const uint32_t*)vt,
        (uint32_t*)attn);

    gemm16<<<dim3(D_ / 128, M / 128), 256>>>(
        (const uint32_t*)attn, (const uint32_t*)wot, out, D_, NHH);
}